// round 12
// baseline (speedup 1.0000x reference)
#include <cuda_runtime.h>
#include <cfloat>
#include <cstdint>

#define Bz 4
#define NN0 8192
#define NN1 2048
#define NN2 512
#define NN3 128

typedef unsigned long long u64;

__device__ __forceinline__ u64 pack2(float x, float y) {
    u64 r; asm("mov.b64 %0, {%1, %2};" : "=l"(r) : "f"(x), "f"(y)); return r;
}
__device__ __forceinline__ float2 unpack2(u64 v) {
    float2 r; asm("mov.b64 {%0, %1}, %2;" : "=f"(r.x), "=f"(r.y) : "l"(v)); return r;
}
__device__ __forceinline__ u64 ffma2(u64 a, u64 b, u64 c) {
    u64 d; asm("fma.rn.f32x2 %0, %1, %2, %3;" : "=l"(d) : "l"(a), "l"(b), "l"(c)); return d;
}
__device__ __forceinline__ unsigned ordf(float f) {
    unsigned b = __float_as_uint(f);
    return b ^ (((unsigned)((int)b >> 31)) | 0x80000000u);
}
__device__ __forceinline__ float unordf(unsigned m) {
    unsigned b = m ^ ((m & 0x80000000u) ? 0x80000000u : 0xffffffffu);
    return __uint_as_float(b);
}

#define INS3(u, si) do { \
    bool p1 = (u) < m1v; \
    unsigned c1v = p1 ? m1v : (u);  int c1s = p1 ? m1s : (si); \
    m1v = p1 ? (u) : m1v;           m1s = p1 ? (si) : m1s; \
    bool p2 = c1v < m2v; \
    unsigned c2v = p2 ? m2v : c1v;  int c2s = p2 ? m2s : c1s; \
    m2v = p2 ? c1v : m2v;           m2s = p2 ? c1s : m2s; \
    bool p3 = c2v < m3v; \
    m3v = p3 ? c2v : m3v;           m3s = p3 ? c2s : m3s; \
} while(0)

#define FMA16(acc, w, F0, F1, F2, F3) do { \
    acc[0]=ffma2(F0.x,(w),acc[0]); acc[1]=ffma2(F0.y,(w),acc[1]); \
    acc[2]=ffma2(F1.x,(w),acc[2]); acc[3]=ffma2(F1.y,(w),acc[3]); \
    acc[4]=ffma2(F2.x,(w),acc[4]); acc[5]=ffma2(F2.y,(w),acc[5]); \
    acc[6]=ffma2(F3.x,(w),acc[6]); acc[7]=ffma2(F3.y,(w),acc[7]); \
} while(0)

// 8 FFMA2 macro (half-neighbor slice)
#define FMA8(acc, w, F0, F1) do { \
    acc[0]=ffma2(F0.x,(w),acc[0]); acc[1]=ffma2(F0.y,(w),acc[1]); \
    acc[2]=ffma2(F1.x,(w),acc[2]); acc[3]=ffma2(F1.y,(w),acc[3]); \
} while(0)

// ---------------- scratch (allocation-free) ----------------
__device__ int   g_idx0[Bz*NN1*16];
__device__ int   g_idx1[Bz*NN2*16];
__device__ int   g_idx2[Bz*NN3*16];
__device__ int   g_uidx0[Bz*NN2*3];
__device__ float g_ud20 [Bz*NN2*3];
__device__ int   g_uidx1[Bz*NN1*3];
__device__ float g_ud21 [Bz*NN1*3];
__device__ int   g_uidx2[Bz*NN0*3];
__device__ float g_ud22 [Bz*NN0*3];
__device__ float g_x1 [Bz*NN1*128];
__device__ float g_x2 [Bz*NN2*256];
__device__ float g_x3 [Bz*NN3*512];
__device__ float g_up0[Bz*NN2*256];
__device__ float g_up1[Bz*NN1*128];
__device__ __align__(16) float g_wdup[2*806656];
__device__ __align__(16) float4 g_pos4[Bz*NN0];

#define OFF_D0W1 0
#define OFF_D0W2 768
#define OFF_D1W1 17152
#define OFF_D1W2 50688
#define OFF_D2W1 116224
#define OFF_D2W2 248832
#define OFF_U0W  510976
#define OFF_U1W  707584
#define OFF_U2W  756736
#define OFF_FW1  773888
#define OFF_FW2  790272
#define W_TOTAL  806656

// ---------------- prep: weight duplication ----------------
__global__ void dup_weights_kernel(const float* __restrict__ s0, const float* __restrict__ s1,
                                   const float* __restrict__ s2, const float* __restrict__ s3,
                                   const float* __restrict__ s4, const float* __restrict__ s5,
                                   const float* __restrict__ s6, const float* __restrict__ s7,
                                   const float* __restrict__ s8, const float* __restrict__ s9,
                                   const float* __restrict__ s10, float* __restrict__ dst) {
    int gid = blockIdx.x*256 + threadIdx.x;
    if (gid >= W_TOTAL) return;
    const int offs[11] = {OFF_D0W1,OFF_D0W2,OFF_D1W1,OFF_D1W2,OFF_D2W1,OFF_D2W2,
                          OFF_U0W,OFF_U1W,OFF_U2W,OFF_FW1,OFF_FW2};
    const float* srcs[11] = {s0,s1,s2,s3,s4,s5,s6,s7,s8,s9,s10};
    int seg = 0;
    #pragma unroll
    for (int i = 1; i < 11; i++) seg = (gid >= offs[i]) ? i : seg;
    float v = srcs[seg][gid - offs[seg]];
    reinterpret_cast<float2*>(dst)[gid] = make_float2(v, v);
}

// ---------------- prep: pos -> (x,y,z,|r|^2) ----------------
__global__ void prep_pos4_kernel(const float* __restrict__ pos, float4* __restrict__ out) {
    int i = blockIdx.x*256 + threadIdx.x;
    float x = pos[3*i+0], y = pos[3*i+1], z = pos[3*i+2];
    float rr = x*x + y*y + z*z;
    out[i] = make_float4(x, y, z, rr);
}

// ---------------- KNN K=16 (R6-validated: CNT=32, NWARP=8) ----------------
template<int CNT, int NWARP>
__global__ void knn16_kernel(const float4* __restrict__ pos4, int Nq, int* __restrict__ oidx) {
    __shared__ u64 skey[NWARP*16];
    int b = blockIdx.y, q = blockIdx.x;
    int lane = threadIdx.x & 31, w = threadIdx.x >> 5;
    const float4* rp = pos4 + (size_t)b*NN0;
    float4 qp = rp[q];
    float qx = qp.x, qy = qp.y, qz = qp.z, qq = qp.w;
    int base = w*CNT*32;

    unsigned ud[CNT];
    unsigned m1v = 0xffffffffu, m2v = 0xffffffffu, m3v = 0xffffffffu;
    int m1s = 0, m2s = 0, m3s = 0;
    #pragma unroll
    for (int i = 0; i < CNT; i++) {
        float4 r4 = rp[base + i*32 + lane];
        float dt = qx*r4.x + qy*r4.y + qz*r4.z;
        float dv = qq + r4.w - 2.0f*dt;
        unsigned u = ordf(dv);
        ud[i] = u;
        INS3(u, i);
    }
    for (int s = 0; s < 16; s++) {
        unsigned mh = __reduce_min_sync(0xffffffffu, m1v);
        unsigned cand = (m1v == mh) ? (unsigned)(m1s*32 + lane) : 0xffffffffu;
        unsigned ml = __reduce_min_sync(0xffffffffu, cand);
        if (lane == 0) skey[w*16 + s] = ((u64)mh << 32) | (unsigned)(base + (int)ml);
        if (cand == ml && m1v == mh) {
            unsigned thr = m1v;
            m1v = m2v; m1s = m2s;
            m2v = m3v; m2s = m3s;
            m3v = 0xffffffffu;
            if (m1v == 0xffffffffu) {   // exhausted buffer: exact rebuild above threshold
                m2v = 0xffffffffu; m3v = 0xffffffffu;
                #pragma unroll
                for (int i = 0; i < CNT; i++) {
                    unsigned u = ud[i];
                    if (u > thr) { INS3(u, i); }
                }
            }
        }
    }
    __syncthreads();
    if (w == 0) {
        u64 head = ~0ull; int ptr = 0;
        if (lane < NWARP) head = skey[lane*16];
        size_t obase = ((size_t)b*Nq + q)*16;
        for (int s = 0; s < 16; s++) {
            unsigned hi = (unsigned)(head >> 32);
            unsigned mh = __reduce_min_sync(0xffffffffu, hi);
            unsigned lo = (hi == mh) ? (unsigned)head : 0xffffffffu;
            unsigned ml = __reduce_min_sync(0xffffffffu, lo);
            if (lane == 0) oidx[obase + s] = (int)ml;
            u64 best = ((u64)mh << 32) | ml;
            if (head == best) {
                ptr++;
                head = (ptr < 16) ? skey[lane*16 + ptr] : ~0ull;
            }
        }
    }
}

// ---------------- KNN K=3, block variant (large Nr) ----------------
template<int CNT, int NWARP>
__global__ void knn3b_kernel(const float4* __restrict__ pos4, int Nq,
                             int* __restrict__ oidx, float* __restrict__ od2) {
    __shared__ u64 skey[NWARP*3];
    int b = blockIdx.y, q = blockIdx.x;
    int lane = threadIdx.x & 31, w = threadIdx.x >> 5;
    const float4* rp = pos4 + (size_t)b*NN0;
    float4 qp = rp[q];
    float qx = qp.x, qy = qp.y, qz = qp.z, qq = qp.w;
    int base = w*CNT*32;

    unsigned m1v = 0xffffffffu, m2v = 0xffffffffu, m3v = 0xffffffffu;
    int m1s = 0, m2s = 0, m3s = 0;
    #pragma unroll
    for (int i = 0; i < CNT; i++) {
        float4 r4 = rp[base + i*32 + lane];
        float dt = qx*r4.x + qy*r4.y + qz*r4.z;
        float dv = qq + r4.w - 2.0f*dt;
        unsigned u = ordf(dv);
        INS3(u, i);
    }
    #pragma unroll
    for (int s = 0; s < 3; s++) {
        unsigned mh = __reduce_min_sync(0xffffffffu, m1v);
        unsigned cand = (m1v == mh) ? (unsigned)(m1s*32 + lane) : 0xffffffffu;
        unsigned ml = __reduce_min_sync(0xffffffffu, cand);
        if (lane == 0) skey[w*3 + s] = ((u64)mh << 32) | (unsigned)(base + (int)ml);
        if (cand == ml && m1v == mh) {
            m1v = m2v; m1s = m2s;
            m2v = m3v; m2s = m3s;
            m3v = 0xffffffffu;
        }
    }
    __syncthreads();
    if (w == 0) {
        u64 head = ~0ull; int ptr = 0;
        if (lane < NWARP) head = skey[lane*3];
        size_t obase = ((size_t)b*Nq + q)*3;
        #pragma unroll
        for (int s = 0; s < 3; s++) {
            unsigned hi = (unsigned)(head >> 32);
            unsigned mh = __reduce_min_sync(0xffffffffu, hi);
            unsigned lo = (hi == mh) ? (unsigned)head : 0xffffffffu;
            unsigned ml = __reduce_min_sync(0xffffffffu, lo);
            if (lane == 0) {
                oidx[obase + s] = (int)ml;
                od2[obase + s]  = fmaxf(unordf(mh), 0.0f);
            }
            u64 best = ((u64)mh << 32) | ml;
            if (head == best) {
                ptr++;
                head = (ptr < 3) ? skey[lane*3 + ptr] : ~0ull;
            }
        }
    }
}

// ---------------- KNN K=3, warp variant (small Nr) ----------------
template<int CNT>
__global__ void knn3_kernel(const float4* __restrict__ pos4, int Nq,
                            int* __restrict__ oidx, float* __restrict__ od2) {
    int b = blockIdx.y;
    int lane = threadIdx.x & 31;
    int q = blockIdx.x*8 + (threadIdx.x >> 5);
    const float4* rp = pos4 + (size_t)b*NN0;
    float4 qp = rp[q];
    float qx = qp.x, qy = qp.y, qz = qp.z, qq = qp.w;

    unsigned m1v = 0xffffffffu, m2v = 0xffffffffu, m3v = 0xffffffffu;
    int m1s = 0, m2s = 0, m3s = 0;
    #pragma unroll
    for (int i = 0; i < CNT; i++) {
        float4 r4 = rp[i*32 + lane];
        float dt = qx*r4.x + qy*r4.y + qz*r4.z;
        float dv = qq + r4.w - 2.0f*dt;
        unsigned u = ordf(dv);
        INS3(u, i);
    }
    size_t obase = ((size_t)b*Nq + q)*3;
    #pragma unroll
    for (int s = 0; s < 3; s++) {
        unsigned mh = __reduce_min_sync(0xffffffffu, m1v);
        unsigned cand = (m1v == mh) ? (unsigned)(m1s*32 + lane) : 0xffffffffu;
        unsigned ml = __reduce_min_sync(0xffffffffu, cand);
        if (lane == 0) {
            oidx[obase + s] = (int)ml;
            od2[obase + s]  = fmaxf(unordf(mh), 0.0f);
        }
        if (cand == ml && m1v == mh) {
            m1v = m2v; m1s = m2s;
            m2v = m3v; m2s = m3s;
            m3v = 0xffffffffu;
        }
    }
}

// ---------------- down0 k-split: 128 threads, half-group owns 8 of 16 neighbors ----
// j-block=2, 4 u64 accumulators per channel -> ~44 regs -> ~60% occupancy.
__global__ void down0s_kernel(const float* __restrict__ xprev, const float* __restrict__ pos,
                              const int* __restrict__ idx,
                              const float* __restrict__ W1d, const float* __restrict__ b1,
                              const float* __restrict__ W2d, const float* __restrict__ b2,
                              float* __restrict__ xout) {
    __shared__ float featT[6*16];
    __shared__ float hT[128*16];
    __shared__ float pmax[2][128];
    __shared__ int nbs[16];
    int b = blockIdx.y, q = blockIdx.x;
    int tid = threadIdx.x;
    int h = tid >> 6, t = tid & 63;
    if (tid < 16) nbs[tid] = idx[((size_t)b*NN1 + q)*16 + tid];
    __syncthreads();
    const float* rp = pos + (size_t)b*NN0*3;
    float cx = rp[3*q+0], cy = rp[3*q+1], cz = rp[3*q+2];
    const float* xp = xprev + (size_t)b*NN0*3;
    if (tid < 96) {
        int d = tid >> 4, k = tid & 15;
        int nb = nbs[k];
        float v;
        if      (d == 0) v = rp[3*nb+0] - cx;
        else if (d == 1) v = rp[3*nb+1] - cy;
        else if (d == 2) v = rp[3*nb+2] - cz;
        else             v = xp[3*nb + (d-3)];
        featT[d*16 + k] = v;
    }
    __syncthreads();
    int j0 = 2*t;
    int koff = 8*h;       // this group's neighbor slice
    u64 a0[4], a1[4];
    // ---- layer 1 (CIN=6) ----
    {
        float2 bb = *reinterpret_cast<const float2*>(&b1[j0]);
        u64 p0 = pack2(bb.x, bb.x), p1 = pack2(bb.y, bb.y);
        #pragma unroll
        for (int i = 0; i < 4; i++) { a0[i] = p0; a1[i] = p1; }
    }
    #pragma unroll
    for (int d = 0; d < 6; d++) {
        ulonglong2 w = *reinterpret_cast<const ulonglong2*>(W1d + 2*(d*128 + j0));
        const ulonglong2* f = reinterpret_cast<const ulonglong2*>(featT + d*16 + koff);
        ulonglong2 f0 = f[0], f1 = f[1];
        FMA8(a0, w.x, f0, f1);
        FMA8(a1, w.y, f0, f1);
    }
    {
        float4* h0 = reinterpret_cast<float4*>(hT + (size_t)j0*16 + koff);
        float4* h1 = reinterpret_cast<float4*>(hT + (size_t)(j0+1)*16 + koff);
        #pragma unroll
        for (int i = 0; i < 2; i++) {
            float2 x0 = unpack2(a0[2*i]), x1 = unpack2(a0[2*i+1]);
            h0[i] = make_float4(fmaxf(x0.x,0.f), fmaxf(x0.y,0.f), fmaxf(x1.x,0.f), fmaxf(x1.y,0.f));
            float2 y0 = unpack2(a1[2*i]), y1 = unpack2(a1[2*i+1]);
            h1[i] = make_float4(fmaxf(y0.x,0.f), fmaxf(y0.y,0.f), fmaxf(y1.x,0.f), fmaxf(y1.y,0.f));
        }
    }
    __syncthreads();
    // ---- layer 2 (128 -> 128 over 8 neighbors) ----
    {
        float2 bb = *reinterpret_cast<const float2*>(&b2[j0]);
        u64 p0 = pack2(bb.x, bb.x), p1 = pack2(bb.y, bb.y);
        #pragma unroll
        for (int i = 0; i < 4; i++) { a0[i] = p0; a1[i] = p1; }
    }
    #pragma unroll 4
    for (int d = 0; d < 128; d++) {
        ulonglong2 w = *reinterpret_cast<const ulonglong2*>(W2d + 2*(d*128 + j0));
        const ulonglong2* f = reinterpret_cast<const ulonglong2*>(hT + d*16 + koff);
        ulonglong2 f0 = f[0], f1 = f[1];
        FMA8(a0, w.x, f0, f1);
        FMA8(a1, w.y, f0, f1);
    }
    // ---- partial max over this group's 8 neighbors ----
    float m0 = -FLT_MAX, m1 = -FLT_MAX;
    #pragma unroll
    for (int i = 0; i < 4; i++) {
        float2 x = unpack2(a0[i]); m0 = fmaxf(m0, fmaxf(x.x, x.y));
        float2 y = unpack2(a1[i]); m1 = fmaxf(m1, fmaxf(y.x, y.y));
    }
    pmax[h][j0]   = m0;
    pmax[h][j0+1] = m1;
    __syncthreads();
    if (h == 0) {
        float r0 = fmaxf(pmax[0][j0],   pmax[1][j0]);
        float r1 = fmaxf(pmax[0][j0+1], pmax[1][j0+1]);
        *reinterpret_cast<float2*>(&xout[((size_t)b*NN1 + q)*128 + j0]) = make_float2(r0, r1);
    }
}

// ---------------- down: gather + 2-layer MLP + max over 16 (one center, j-block=2) ----------------
template<int C_PREV, int C_HID>
__global__ void down_kernel(const float* __restrict__ xprev, const float* __restrict__ pos,
                            const int* __restrict__ idx,
                            const float* __restrict__ W1d, const float* __restrict__ b1,
                            const float* __restrict__ W2d, const float* __restrict__ b2,
                            float* __restrict__ xout, int Nq, int xbs) {
    constexpr int CIN = 3 + C_PREV;
    extern __shared__ float sm[];
    float* featT = sm;               // CIN*16
    float* hT    = sm + CIN*16;      // C_HID*16
    __shared__ int nbs[16];
    int b = blockIdx.y, q = blockIdx.x;
    if (threadIdx.x < 16) nbs[threadIdx.x] = idx[((size_t)b*Nq + q)*16 + threadIdx.x];
    __syncthreads();
    const float* rp = pos + (size_t)b*NN0*3;
    float cx = rp[3*q+0], cy = rp[3*q+1], cz = rp[3*q+2];
    const float* xp = xprev + (size_t)b*xbs;
    for (int e = threadIdx.x; e < 16*CIN; e += blockDim.x) {
        int d = e >> 4, k = e & 15;
        int nb = nbs[k];
        float v;
        if      (d == 0) v = rp[3*nb+0] - cx;
        else if (d == 1) v = rp[3*nb+1] - cy;
        else if (d == 2) v = rp[3*nb+2] - cz;
        else             v = xp[(size_t)nb*C_PREV + (d-3)];
        featT[d*16 + k] = v;
    }
    __syncthreads();
    int j0 = 2*threadIdx.x;
    u64 a0[8], a1[8];
    {
        float2 bb = *reinterpret_cast<const float2*>(&b1[j0]);
        u64 p0 = pack2(bb.x, bb.x), p1 = pack2(bb.y, bb.y);
        #pragma unroll
        for (int i = 0; i < 8; i++) { a0[i] = p0; a1[i] = p1; }
    }
    #pragma unroll 2
    for (int d = 0; d < CIN; d++) {
        ulonglong2 w = *reinterpret_cast<const ulonglong2*>(W1d + 2*(d*C_HID + j0));
        const ulonglong2* f = reinterpret_cast<const ulonglong2*>(featT + d*16);
        ulonglong2 f0 = f[0], f1 = f[1], f2 = f[2], f3 = f[3];
        FMA16(a0, w.x, f0, f1, f2, f3);
        FMA16(a1, w.y, f0, f1, f2, f3);
    }
    {
        float4* h0 = reinterpret_cast<float4*>(hT + (size_t)j0*16);
        float4* h1 = reinterpret_cast<float4*>(hT + (size_t)(j0+1)*16);
        #pragma unroll
        for (int i = 0; i < 4; i++) {
            float2 x0 = unpack2(a0[2*i]), x1 = unpack2(a0[2*i+1]);
            h0[i] = make_float4(fmaxf(x0.x,0.f), fmaxf(x0.y,0.f), fmaxf(x1.x,0.f), fmaxf(x1.y,0.f));
            float2 y0 = unpack2(a1[2*i]), y1 = unpack2(a1[2*i+1]);
            h1[i] = make_float4(fmaxf(y0.x,0.f), fmaxf(y0.y,0.f), fmaxf(y1.x,0.f), fmaxf(y1.y,0.f));
        }
    }
    __syncthreads();
    {
        float2 bb = *reinterpret_cast<const float2*>(&b2[j0]);
        u64 p0 = pack2(bb.x, bb.x), p1 = pack2(bb.y, bb.y);
        #pragma unroll
        for (int i = 0; i < 8; i++) { a0[i] = p0; a1[i] = p1; }
    }
    #pragma unroll 2
    for (int d = 0; d < C_HID; d++) {
        ulonglong2 w = *reinterpret_cast<const ulonglong2*>(W2d + 2*(d*C_HID + j0));
        const ulonglong2* f = reinterpret_cast<const ulonglong2*>(hT + d*16);
        ulonglong2 f0 = f[0], f1 = f[1], f2 = f[2], f3 = f[3];
        FMA16(a0, w.x, f0, f1, f2, f3);
        FMA16(a1, w.y, f0, f1, f2, f3);
    }
    float m0 = -FLT_MAX, m1 = -FLT_MAX;
    #pragma unroll
    for (int i = 0; i < 8; i++) {
        float2 x = unpack2(a0[i]); m0 = fmaxf(m0, fmaxf(x.x, x.y));
        float2 y = unpack2(a1[i]); m1 = fmaxf(m1, fmaxf(y.x, y.y));
    }
    *reinterpret_cast<float2*>(&xout[((size_t)b*Nq + q)*C_HID + j0]) = make_float2(m0, m1);
}

// ---------------- up: 3-NN inverse-distance interp + cat + linear + relu ----------------
template<int C_XC, int C_PRV, int C_OUT>
__global__ void up_kernel(const float* __restrict__ xc, const float* __restrict__ prv,
                          const int* __restrict__ idx, const float* __restrict__ d2,
                          const float* __restrict__ Wd, const float* __restrict__ bias,
                          float* __restrict__ out, int Nq, int Nc) {
    constexpr int CIN = C_XC + C_PRV;
    constexpr int QT = 16;
    extern __shared__ float sm[];
    float* featT = sm;
    __shared__ float wsh[QT][3];
    __shared__ int   ish[QT][3];
    int b = blockIdx.y;
    int q0 = blockIdx.x * QT;
    if (threadIdx.x < QT) {
        int q = q0 + threadIdx.x;
        size_t base = ((size_t)b*Nq + q)*3;
        float w0 = 1.0f/(d2[base+0] + 1e-8f);
        float w1 = 1.0f/(d2[base+1] + 1e-8f);
        float w2 = 1.0f/(d2[base+2] + 1e-8f);
        float s = w0 + w1 + w2;
        wsh[threadIdx.x][0] = w0/s; wsh[threadIdx.x][1] = w1/s; wsh[threadIdx.x][2] = w2/s;
        ish[threadIdx.x][0] = idx[base+0]; ish[threadIdx.x][1] = idx[base+1]; ish[threadIdx.x][2] = idx[base+2];
    }
    __syncthreads();
    const float* xcb = xc + (size_t)b*Nc*C_XC;
    for (int e = threadIdx.x; e < CIN*QT; e += blockDim.x) {
        int d = e >> 4, qq = e & 15;
        float v;
        if (d < C_XC) {
            v = wsh[qq][0]*xcb[(size_t)ish[qq][0]*C_XC + d]
              + wsh[qq][1]*xcb[(size_t)ish[qq][1]*C_XC + d]
              + wsh[qq][2]*xcb[(size_t)ish[qq][2]*C_XC + d];
        } else {
            v = prv[((size_t)b*Nq + q0 + qq)*C_PRV + (d - C_XC)];
        }
        featT[e] = v;
    }
    __syncthreads();
    int j0 = 2*threadIdx.x;
    u64 a0[8], a1[8];
    {
        float2 bb = *reinterpret_cast<const float2*>(&bias[j0]);
        u64 p0 = pack2(bb.x, bb.x), p1 = pack2(bb.y, bb.y);
        #pragma unroll
        for (int i = 0; i < 8; i++) { a0[i] = p0; a1[i] = p1; }
    }
    #pragma unroll 2
    for (int d = 0; d < CIN; d++) {
        ulonglong2 w = *reinterpret_cast<const ulonglong2*>(Wd + 2*(d*C_OUT + j0));
        const ulonglong2* f = reinterpret_cast<const ulonglong2*>(featT + d*QT);
        ulonglong2 f0 = f[0], f1 = f[1], f2 = f[2], f3 = f[3];
        FMA16(a0, w.x, f0, f1, f2, f3);
        FMA16(a1, w.y, f0, f1, f2, f3);
    }
    size_t obase = ((size_t)b*Nq + q0)*C_OUT + j0;
    #pragma unroll
    for (int i = 0; i < 8; i++) {
        float2 x = unpack2(a0[i]), y = unpack2(a1[i]);
        *reinterpret_cast<float2*>(&out[obase + (size_t)(2*i+0)*C_OUT]) =
            make_float2(fmaxf(x.x,0.f), fmaxf(y.x,0.f));
        *reinterpret_cast<float2*>(&out[obase + (size_t)(2*i+1)*C_OUT]) =
            make_float2(fmaxf(x.y,0.f), fmaxf(y.y,0.f));
    }
}

// ---------------- fused: up2 + final MLP (QT=16, 64 threads) ----------------
__global__ void up2_final_kernel(const float* __restrict__ up1,
                                 const float* __restrict__ x0, const float* __restrict__ pos0,
                                 const int* __restrict__ idx, const float* __restrict__ d2,
                                 const float* __restrict__ u2Wd, const float* __restrict__ u2b,
                                 const float* __restrict__ fW1d, const float* __restrict__ fb1,
                                 const float* __restrict__ fW2d, const float* __restrict__ fb2,
                                 float* __restrict__ out) {
    constexpr int QT = 16;
    __shared__ float featT[134*QT];
    __shared__ float h1T[128*QT];
    __shared__ float wsh[QT][3];
    __shared__ int   ish[QT][3];
    int b = blockIdx.y;
    int q0 = blockIdx.x * QT;
    if (threadIdx.x < QT) {
        int q = q0 + threadIdx.x;
        size_t base = ((size_t)b*NN0 + q)*3;
        float w0 = 1.0f/(d2[base+0] + 1e-8f);
        float w1 = 1.0f/(d2[base+1] + 1e-8f);
        float w2 = 1.0f/(d2[base+2] + 1e-8f);
        float s = w0 + w1 + w2;
        wsh[threadIdx.x][0] = w0/s; wsh[threadIdx.x][1] = w1/s; wsh[threadIdx.x][2] = w2/s;
        ish[threadIdx.x][0] = idx[base+0]; ish[threadIdx.x][1] = idx[base+1]; ish[threadIdx.x][2] = idx[base+2];
    }
    __syncthreads();
    const float* xcb = up1 + (size_t)b*NN1*128;
    for (int e = threadIdx.x; e < 134*QT; e += 64) {
        int d = e >> 4, qq = e & 15;
        float v;
        if (d < 128) {
            v = wsh[qq][0]*xcb[(size_t)ish[qq][0]*128 + d]
              + wsh[qq][1]*xcb[(size_t)ish[qq][1]*128 + d]
              + wsh[qq][2]*xcb[(size_t)ish[qq][2]*128 + d];
        } else if (d < 131) {
            v = x0  [((size_t)b*NN0 + q0 + qq)*3 + (d-128)];
        } else {
            v = pos0[((size_t)b*NN0 + q0 + qq)*3 + (d-131)];
        }
        featT[e] = v;
    }
    __syncthreads();
    int j0 = 2*threadIdx.x;
    u64 a0[8], a1[8];

    {
        float2 bb = *reinterpret_cast<const float2*>(&u2b[j0]);
        u64 p0 = pack2(bb.x, bb.x), p1 = pack2(bb.y, bb.y);
        #pragma unroll
        for (int i = 0; i < 8; i++) { a0[i] = p0; a1[i] = p1; }
    }
    #pragma unroll 2
    for (int d = 0; d < 134; d++) {
        ulonglong2 w = *reinterpret_cast<const ulonglong2*>(u2Wd + 2*(d*128 + j0));
        const ulonglong2* f = reinterpret_cast<const ulonglong2*>(featT + d*QT);
        ulonglong2 f0 = f[0], f1 = f[1], f2 = f[2], f3 = f[3];
        FMA16(a0, w.x, f0, f1, f2, f3);
        FMA16(a1, w.y, f0, f1, f2, f3);
    }
    {
        float4* h0 = reinterpret_cast<float4*>(h1T + (size_t)j0*QT);
        float4* h1 = reinterpret_cast<float4*>(h1T + (size_t)(j0+1)*QT);
        #pragma unroll
        for (int i = 0; i < 4; i++) {
            float2 x0v = unpack2(a0[2*i]), x1v = unpack2(a0[2*i+1]);
            h0[i] = make_float4(fmaxf(x0v.x,0.f), fmaxf(x0v.y,0.f), fmaxf(x1v.x,0.f), fmaxf(x1v.y,0.f));
            float2 y0v = unpack2(a1[2*i]), y1v = unpack2(a1[2*i+1]);
            h1[i] = make_float4(fmaxf(y0v.x,0.f), fmaxf(y0v.y,0.f), fmaxf(y1v.x,0.f), fmaxf(y1v.y,0.f));
        }
    }
    __syncthreads();

    {
        float2 bb = *reinterpret_cast<const float2*>(&fb1[j0]);
        u64 p0 = pack2(bb.x, bb.x), p1 = pack2(bb.y, bb.y);
        #pragma unroll
        for (int i = 0; i < 8; i++) { a0[i] = p0; a1[i] = p1; }
    }
    #pragma unroll 2
    for (int d = 0; d < 128; d++) {
        ulonglong2 w = *reinterpret_cast<const ulonglong2*>(fW1d + 2*(d*128 + j0));
        const ulonglong2* f = reinterpret_cast<const ulonglong2*>(h1T + d*QT);
        ulonglong2 f0 = f[0], f1 = f[1], f2 = f[2], f3 = f[3];
        FMA16(a0, w.x, f0, f1, f2, f3);
        FMA16(a1, w.y, f0, f1, f2, f3);
    }
    __syncthreads();
    {
        float4* h0 = reinterpret_cast<float4*>(featT + (size_t)j0*QT);
        float4* h1 = reinterpret_cast<float4*>(featT + (size_t)(j0+1)*QT);
        #pragma unroll
        for (int i = 0; i < 4; i++) {
            float2 x0v = unpack2(a0[2*i]), x1v = unpack2(a0[2*i+1]);
            h0[i] = make_float4(fmaxf(x0v.x,0.f), fmaxf(x0v.y,0.f), fmaxf(x1v.x,0.f), fmaxf(x1v.y,0.f));
            float2 y0v = unpack2(a1[2*i]), y1v = unpack2(a1[2*i+1]);
            h1[i] = make_float4(fmaxf(y0v.x,0.f), fmaxf(y0v.y,0.f), fmaxf(y1v.x,0.f), fmaxf(y1v.y,0.f));
        }
    }
    __syncthreads();

    {
        float2 bb = *reinterpret_cast<const float2*>(&fb2[j0]);
        u64 p0 = pack2(bb.x, bb.x), p1 = pack2(bb.y, bb.y);
        #pragma unroll
        for (int i = 0; i < 8; i++) { a0[i] = p0; a1[i] = p1; }
    }
    #pragma unroll 2
    for (int d = 0; d < 128; d++) {
        ulonglong2 w = *reinterpret_cast<const ulonglong2*>(fW2d + 2*(d*128 + j0));
        const ulonglong2* f = reinterpret_cast<const ulonglong2*>(featT + d*QT);
        ulonglong2 f0 = f[0], f1 = f[1], f2 = f[2], f3 = f[3];
        FMA16(a0, w.x, f0, f1, f2, f3);
        FMA16(a1, w.y, f0, f1, f2, f3);
    }
    size_t obase = ((size_t)b*NN0 + q0)*128 + j0;
    #pragma unroll
    for (int i = 0; i < 8; i++) {
        float2 x = unpack2(a0[i]), y = unpack2(a1[i]);
        *reinterpret_cast<float2*>(&out[obase + (size_t)(2*i+0)*128]) = make_float2(x.x, y.x);
        *reinterpret_cast<float2*>(&out[obase + (size_t)(2*i+1)*128]) = make_float2(x.y, y.y);
    }
}

// ---------------- host launch ----------------
extern "C" void kernel_launch(void* const* d_in, const int* in_sizes, int n_in,
                              void* d_out, int out_size) {
    const float* x    = (const float*)d_in[0];
    const float* pos  = (const float*)d_in[1];
    const float* d0W1 = (const float*)d_in[2];
    const float* d0b1 = (const float*)d_in[3];
    const float* d0W2 = (const float*)d_in[4];
    const float* d0b2 = (const float*)d_in[5];
    const float* d1W1 = (const float*)d_in[6];
    const float* d1b1 = (const float*)d_in[7];
    const float* d1W2 = (const float*)d_in[8];
    const float* d1b2 = (const float*)d_in[9];
    const float* d2W1 = (const float*)d_in[10];
    const float* d2b1 = (const float*)d_in[11];
    const float* d2W2 = (const float*)d_in[12];
    const float* d2b2 = (const float*)d_in[13];
    const float* u0W  = (const float*)d_in[14];
    const float* u0b  = (const float*)d_in[15];
    const float* u1W  = (const float*)d_in[16];
    const float* u1b  = (const float*)d_in[17];
    const float* u2W  = (const float*)d_in[18];
    const float* u2b  = (const float*)d_in[19];
    const float* fW1  = (const float*)d_in[20];
    const float* fb1  = (const float*)d_in[21];
    const float* fW2  = (const float*)d_in[22];
    const float* fb2  = (const float*)d_in[23];
    float* out = (float*)d_out;

    int *idx0, *idx1, *idx2, *uidx0, *uidx1, *uidx2;
    float *ud20, *ud21, *ud22, *x1, *x2, *x3, *up0, *up1, *wd;
    float4* pos4;
    cudaGetSymbolAddress((void**)&idx0,  g_idx0);
    cudaGetSymbolAddress((void**)&idx1,  g_idx1);
    cudaGetSymbolAddress((void**)&idx2,  g_idx2);
    cudaGetSymbolAddress((void**)&uidx0, g_uidx0);
    cudaGetSymbolAddress((void**)&uidx1, g_uidx1);
    cudaGetSymbolAddress((void**)&uidx2, g_uidx2);
    cudaGetSymbolAddress((void**)&ud20,  g_ud20);
    cudaGetSymbolAddress((void**)&ud21,  g_ud21);
    cudaGetSymbolAddress((void**)&ud22,  g_ud22);
    cudaGetSymbolAddress((void**)&x1,    g_x1);
    cudaGetSymbolAddress((void**)&x2,    g_x2);
    cudaGetSymbolAddress((void**)&x3,    g_x3);
    cudaGetSymbolAddress((void**)&up0,   g_up0);
    cudaGetSymbolAddress((void**)&up1,   g_up1);
    cudaGetSymbolAddress((void**)&wd,    g_wdup);
    cudaGetSymbolAddress((void**)&pos4,  g_pos4);

    const float* d0W1d = wd + 2*OFF_D0W1;
    const float* d0W2d = wd + 2*OFF_D0W2;
    const float* d1W1d = wd + 2*OFF_D1W1;
    const float* d1W2d = wd + 2*OFF_D1W2;
    const float* d2W1d = wd + 2*OFF_D2W1;
    const float* d2W2d = wd + 2*OFF_D2W2;
    const float* u0Wd  = wd + 2*OFF_U0W;
    const float* u1Wd  = wd + 2*OFF_U1W;
    const float* u2Wd  = wd + 2*OFF_U2W;
    const float* fW1d  = wd + 2*OFF_FW1;
    const float* fW2d  = wd + 2*OFF_FW2;

    cudaFuncSetAttribute((const void*)down_kernel<256,512>,
                         cudaFuncAttributeMaxDynamicSharedMemorySize, 56*1024);
    cudaFuncSetAttribute((const void*)up_kernel<512,256,256>,
                         cudaFuncAttributeMaxDynamicSharedMemorySize, 50*1024);

    // ---- preps ----
    prep_pos4_kernel<<<(Bz*NN0)/256, 256>>>(pos, pos4);
    dup_weights_kernel<<<(W_TOTAL+255)/256, 256>>>(
        d0W1,d0W2,d1W1,d1W2,d2W1,d2W2,u0W,u1W,u2W,fW1,fW2, wd);

    // ---- down 0: knn(2048 q, 8192 refs) + MLP (k-split, 128 threads) ----
    knn16_kernel<32,8><<<dim3(NN1,Bz), 256>>>(pos4, NN1, idx0);
    down0s_kernel<<<dim3(NN1,Bz), 128>>>(x, pos, idx0, d0W1d,d0b1, d0W2d,d0b2, x1);
    // ---- down 1: knn(512 q, 2048 refs) + MLP ----
    knn16_kernel<8,8><<<dim3(NN2,Bz), 256>>>(pos4, NN2, idx1);
    down_kernel<128,256><<<dim3(NN2,Bz), 128, (131*16 + 256*16)*sizeof(float)>>>(
        x1, pos, idx1, d1W1d,d1b1, d1W2d,d1b2, x2, NN2, NN1*128);
    // ---- down 2: knn(128 q, 512 refs) + MLP ----
    knn16_kernel<2,8><<<dim3(NN3,Bz), 256>>>(pos4, NN3, idx2);
    down_kernel<256,512><<<dim3(NN3,Bz), 256, (259*16 + 512*16)*sizeof(float)>>>(
        x2, pos, idx2, d2W1d,d2b1, d2W2d,d2b2, x3, NN3, NN2*256);
    // ---- up 0: knn(512 q, 128 refs) + interp/MLP ----
    knn3_kernel<4><<<dim3(NN2/8,Bz), 256>>>(pos4, NN2, uidx0, ud20);
    up_kernel<512,256,256><<<dim3(NN2/16,Bz), 128, 768*16*sizeof(float)>>>(
        x3, x2, uidx0, ud20, u0Wd, u0b, up0, NN2, NN3);
    // ---- up 1: knn(2048 q, 512 refs) + interp/MLP ----
    knn3_kernel<16><<<dim3(NN1/8,Bz), 256>>>(pos4, NN1, uidx1, ud21);
    up_kernel<256,128,128><<<dim3(NN1/16,Bz), 64, 384*16*sizeof(float)>>>(
        up0, x1, uidx1, ud21, u1Wd, u1b, up1, NN1, NN2);
    // ---- up 2 + final MLP: knn(8192 q, 2048 refs) + fused ----
    knn3b_kernel<8,8><<<dim3(NN0,Bz), 256>>>(pos4, NN0, uidx2, ud22);
    up2_final_kernel<<<dim3(NN0/16,Bz), 64>>>(up1, x, pos, uidx2, ud22,
                                              u2Wd,u2b, fW1d,fb1, fW2d,fb2, out);
    // ---- second tuple element: pos0 passthrough ----
    if (out_size >= Bz*NN0*128 + Bz*NN0*3) {
        cudaMemcpyAsync(out + (size_t)Bz*NN0*128, pos,
                        (size_t)Bz*NN0*3*sizeof(float), cudaMemcpyDeviceToDevice);
    }
}

// round 13
// speedup vs baseline: 1.0876x; 1.0876x over previous
#include <cuda_runtime.h>
#include <cfloat>
#include <cstdint>

#define Bz 4
#define NN0 8192
#define NN1 2048
#define NN2 512
#define NN3 128

typedef unsigned long long u64;

__device__ __forceinline__ u64 pack2(float x, float y) {
    u64 r; asm("mov.b64 %0, {%1, %2};" : "=l"(r) : "f"(x), "f"(y)); return r;
}
__device__ __forceinline__ float2 unpack2(u64 v) {
    float2 r; asm("mov.b64 {%0, %1}, %2;" : "=f"(r.x), "=f"(r.y) : "l"(v)); return r;
}
__device__ __forceinline__ u64 ffma2(u64 a, u64 b, u64 c) {
    u64 d; asm("fma.rn.f32x2 %0, %1, %2, %3;" : "=l"(d) : "l"(a), "l"(b), "l"(c)); return d;
}
__device__ __forceinline__ unsigned ordf(float f) {
    unsigned b = __float_as_uint(f);
    return b ^ (((unsigned)((int)b >> 31)) | 0x80000000u);
}
__device__ __forceinline__ float unordf(unsigned m) {
    unsigned b = m ^ ((m & 0x80000000u) ? 0x80000000u : 0xffffffffu);
    return __uint_as_float(b);
}

#define INS3(u, si) do { \
    bool p1 = (u) < m1v; \
    unsigned c1v = p1 ? m1v : (u);  int c1s = p1 ? m1s : (si); \
    m1v = p1 ? (u) : m1v;           m1s = p1 ? (si) : m1s; \
    bool p2 = c1v < m2v; \
    unsigned c2v = p2 ? m2v : c1v;  int c2s = p2 ? m2s : c1s; \
    m2v = p2 ? c1v : m2v;           m2s = p2 ? c1s : m2s; \
    bool p3 = c2v < m3v; \
    m3v = p3 ? c2v : m3v;           m3s = p3 ? c2s : m3s; \
} while(0)

#define FMA16(acc, w, F0, F1, F2, F3) do { \
    acc[0]=ffma2(F0.x,(w),acc[0]); acc[1]=ffma2(F0.y,(w),acc[1]); \
    acc[2]=ffma2(F1.x,(w),acc[2]); acc[3]=ffma2(F1.y,(w),acc[3]); \
    acc[4]=ffma2(F2.x,(w),acc[4]); acc[5]=ffma2(F2.y,(w),acc[5]); \
    acc[6]=ffma2(F3.x,(w),acc[6]); acc[7]=ffma2(F3.y,(w),acc[7]); \
} while(0)

// ---------------- scratch (allocation-free) ----------------
__device__ int   g_idx0[Bz*NN1*16];
__device__ int   g_idx1[Bz*NN2*16];
__device__ int   g_idx2[Bz*NN3*16];
__device__ int   g_uidx0[Bz*NN2*3];
__device__ float g_ud20 [Bz*NN2*3];
__device__ int   g_uidx1[Bz*NN1*3];
__device__ float g_ud21 [Bz*NN1*3];
__device__ int   g_uidx2[Bz*NN0*3];
__device__ float g_ud22 [Bz*NN0*3];
__device__ float g_x1 [Bz*NN1*128];
__device__ float g_x2 [Bz*NN2*256];
__device__ float g_x3 [Bz*NN3*512];
__device__ float g_up0[Bz*NN2*256];
__device__ float g_up1[Bz*NN1*128];
__device__ __align__(16) float g_wdup[2*806656];
__device__ __align__(16) float4 g_pos4[Bz*NN0];

#define OFF_D0W1 0
#define OFF_D0W2 768
#define OFF_D1W1 17152
#define OFF_D1W2 50688
#define OFF_D2W1 116224
#define OFF_D2W2 248832
#define OFF_U0W  510976
#define OFF_U1W  707584
#define OFF_U2W  756736
#define OFF_FW1  773888
#define OFF_FW2  790272
#define W_TOTAL  806656

// ---------------- prep: weight duplication ----------------
__global__ void dup_weights_kernel(const float* __restrict__ s0, const float* __restrict__ s1,
                                   const float* __restrict__ s2, const float* __restrict__ s3,
                                   const float* __restrict__ s4, const float* __restrict__ s5,
                                   const float* __restrict__ s6, const float* __restrict__ s7,
                                   const float* __restrict__ s8, const float* __restrict__ s9,
                                   const float* __restrict__ s10, float* __restrict__ dst) {
    int gid = blockIdx.x*256 + threadIdx.x;
    if (gid >= W_TOTAL) return;
    const int offs[11] = {OFF_D0W1,OFF_D0W2,OFF_D1W1,OFF_D1W2,OFF_D2W1,OFF_D2W2,
                          OFF_U0W,OFF_U1W,OFF_U2W,OFF_FW1,OFF_FW2};
    const float* srcs[11] = {s0,s1,s2,s3,s4,s5,s6,s7,s8,s9,s10};
    int seg = 0;
    #pragma unroll
    for (int i = 1; i < 11; i++) seg = (gid >= offs[i]) ? i : seg;
    float v = srcs[seg][gid - offs[seg]];
    reinterpret_cast<float2*>(dst)[gid] = make_float2(v, v);
}

// ---------------- prep: pos -> (x,y,z,|r|^2) ----------------
__global__ void prep_pos4_kernel(const float* __restrict__ pos, float4* __restrict__ out) {
    int i = blockIdx.x*256 + threadIdx.x;
    float x = pos[3*i+0], y = pos[3*i+1], z = pos[3*i+2];
    float rr = x*x + y*y + z*z;
    out[i] = make_float4(x, y, z, rr);
}

// ---------------- KNN K=16 (R6-validated: CNT=32, NWARP=8) ----------------
template<int CNT, int NWARP>
__global__ void knn16_kernel(const float4* __restrict__ pos4, int Nq, int* __restrict__ oidx) {
    __shared__ u64 skey[NWARP*16];
    int b = blockIdx.y, q = blockIdx.x;
    int lane = threadIdx.x & 31, w = threadIdx.x >> 5;
    const float4* rp = pos4 + (size_t)b*NN0;
    float4 qp = rp[q];
    float qx = qp.x, qy = qp.y, qz = qp.z, qq = qp.w;
    int base = w*CNT*32;

    unsigned ud[CNT];
    unsigned m1v = 0xffffffffu, m2v = 0xffffffffu, m3v = 0xffffffffu;
    int m1s = 0, m2s = 0, m3s = 0;
    #pragma unroll
    for (int i = 0; i < CNT; i++) {
        float4 r4 = rp[base + i*32 + lane];
        float dt = qx*r4.x + qy*r4.y + qz*r4.z;
        float dv = qq + r4.w - 2.0f*dt;
        unsigned u = ordf(dv);
        ud[i] = u;
        INS3(u, i);
    }
    for (int s = 0; s < 16; s++) {
        unsigned mh = __reduce_min_sync(0xffffffffu, m1v);
        unsigned cand = (m1v == mh) ? (unsigned)(m1s*32 + lane) : 0xffffffffu;
        unsigned ml = __reduce_min_sync(0xffffffffu, cand);
        if (lane == 0) skey[w*16 + s] = ((u64)mh << 32) | (unsigned)(base + (int)ml);
        if (cand == ml && m1v == mh) {
            unsigned thr = m1v;
            m1v = m2v; m1s = m2s;
            m2v = m3v; m2s = m3s;
            m3v = 0xffffffffu;
            if (m1v == 0xffffffffu) {   // exhausted buffer: exact rebuild above threshold
                m2v = 0xffffffffu; m3v = 0xffffffffu;
                #pragma unroll
                for (int i = 0; i < CNT; i++) {
                    unsigned u = ud[i];
                    if (u > thr) { INS3(u, i); }
                }
            }
        }
    }
    __syncthreads();
    if (w == 0) {
        u64 head = ~0ull; int ptr = 0;
        if (lane < NWARP) head = skey[lane*16];
        size_t obase = ((size_t)b*Nq + q)*16;
        for (int s = 0; s < 16; s++) {
            unsigned hi = (unsigned)(head >> 32);
            unsigned mh = __reduce_min_sync(0xffffffffu, hi);
            unsigned lo = (hi == mh) ? (unsigned)head : 0xffffffffu;
            unsigned ml = __reduce_min_sync(0xffffffffu, lo);
            if (lane == 0) oidx[obase + s] = (int)ml;
            u64 best = ((u64)mh << 32) | ml;
            if (head == best) {
                ptr++;
                head = (ptr < 16) ? skey[lane*16 + ptr] : ~0ull;
            }
        }
    }
}

// ---------------- KNN K=3, warp variant (no register array -> any CNT is safe) ----------------
template<int CNT>
__global__ void knn3_kernel(const float4* __restrict__ pos4, int Nq,
                            int* __restrict__ oidx, float* __restrict__ od2) {
    int b = blockIdx.y;
    int lane = threadIdx.x & 31;
    int q = blockIdx.x*8 + (threadIdx.x >> 5);
    const float4* rp = pos4 + (size_t)b*NN0;
    float4 qp = rp[q];
    float qx = qp.x, qy = qp.y, qz = qp.z, qq = qp.w;

    unsigned m1v = 0xffffffffu, m2v = 0xffffffffu, m3v = 0xffffffffu;
    int m1s = 0, m2s = 0, m3s = 0;
    #pragma unroll 8
    for (int i = 0; i < CNT; i++) {
        float4 r4 = rp[i*32 + lane];
        float dt = qx*r4.x + qy*r4.y + qz*r4.z;
        float dv = qq + r4.w - 2.0f*dt;
        unsigned u = ordf(dv);
        INS3(u, i);
    }
    size_t obase = ((size_t)b*Nq + q)*3;
    #pragma unroll
    for (int s = 0; s < 3; s++) {
        unsigned mh = __reduce_min_sync(0xffffffffu, m1v);
        unsigned cand = (m1v == mh) ? (unsigned)(m1s*32 + lane) : 0xffffffffu;
        unsigned ml = __reduce_min_sync(0xffffffffu, cand);
        if (lane == 0) {
            oidx[obase + s] = (int)ml;
            od2[obase + s]  = fmaxf(unordf(mh), 0.0f);
        }
        if (cand == ml && m1v == mh) {
            m1v = m2v; m1s = m2s;
            m2v = m3v; m2s = m3s;
            m3v = 0xffffffffu;
        }
    }
}

// ---------------- down: gather + 2-layer MLP + max over 16 (one center, j-block=2) ----------------
template<int C_PREV, int C_HID>
__global__ void down_kernel(const float* __restrict__ xprev, const float* __restrict__ pos,
                            const int* __restrict__ idx,
                            const float* __restrict__ W1d, const float* __restrict__ b1,
                            const float* __restrict__ W2d, const float* __restrict__ b2,
                            float* __restrict__ xout, int Nq, int xbs) {
    constexpr int CIN = 3 + C_PREV;
    extern __shared__ float sm[];
    float* featT = sm;               // CIN*16
    float* hT    = sm + CIN*16;      // C_HID*16
    __shared__ int nbs[16];
    int b = blockIdx.y, q = blockIdx.x;
    if (threadIdx.x < 16) nbs[threadIdx.x] = idx[((size_t)b*Nq + q)*16 + threadIdx.x];
    __syncthreads();
    const float* rp = pos + (size_t)b*NN0*3;
    float cx = rp[3*q+0], cy = rp[3*q+1], cz = rp[3*q+2];
    const float* xp = xprev + (size_t)b*xbs;
    for (int e = threadIdx.x; e < 16*CIN; e += blockDim.x) {
        int d = e >> 4, k = e & 15;
        int nb = nbs[k];
        float v;
        if      (d == 0) v = rp[3*nb+0] - cx;
        else if (d == 1) v = rp[3*nb+1] - cy;
        else if (d == 2) v = rp[3*nb+2] - cz;
        else             v = xp[(size_t)nb*C_PREV + (d-3)];
        featT[d*16 + k] = v;
    }
    __syncthreads();
    int j0 = 2*threadIdx.x;
    u64 a0[8], a1[8];
    {
        float2 bb = *reinterpret_cast<const float2*>(&b1[j0]);
        u64 p0 = pack2(bb.x, bb.x), p1 = pack2(bb.y, bb.y);
        #pragma unroll
        for (int i = 0; i < 8; i++) { a0[i] = p0; a1[i] = p1; }
    }
    #pragma unroll 2
    for (int d = 0; d < CIN; d++) {
        ulonglong2 w = *reinterpret_cast<const ulonglong2*>(W1d + 2*(d*C_HID + j0));
        const ulonglong2* f = reinterpret_cast<const ulonglong2*>(featT + d*16);
        ulonglong2 f0 = f[0], f1 = f[1], f2 = f[2], f3 = f[3];
        FMA16(a0, w.x, f0, f1, f2, f3);
        FMA16(a1, w.y, f0, f1, f2, f3);
    }
    {
        float4* h0 = reinterpret_cast<float4*>(hT + (size_t)j0*16);
        float4* h1 = reinterpret_cast<float4*>(hT + (size_t)(j0+1)*16);
        #pragma unroll
        for (int i = 0; i < 4; i++) {
            float2 x0 = unpack2(a0[2*i]), x1 = unpack2(a0[2*i+1]);
            h0[i] = make_float4(fmaxf(x0.x,0.f), fmaxf(x0.y,0.f), fmaxf(x1.x,0.f), fmaxf(x1.y,0.f));
            float2 y0 = unpack2(a1[2*i]), y1 = unpack2(a1[2*i+1]);
            h1[i] = make_float4(fmaxf(y0.x,0.f), fmaxf(y0.y,0.f), fmaxf(y1.x,0.f), fmaxf(y1.y,0.f));
        }
    }
    __syncthreads();
    {
        float2 bb = *reinterpret_cast<const float2*>(&b2[j0]);
        u64 p0 = pack2(bb.x, bb.x), p1 = pack2(bb.y, bb.y);
        #pragma unroll
        for (int i = 0; i < 8; i++) { a0[i] = p0; a1[i] = p1; }
    }
    #pragma unroll 2
    for (int d = 0; d < C_HID; d++) {
        ulonglong2 w = *reinterpret_cast<const ulonglong2*>(W2d + 2*(d*C_HID + j0));
        const ulonglong2* f = reinterpret_cast<const ulonglong2*>(hT + d*16);
        ulonglong2 f0 = f[0], f1 = f[1], f2 = f[2], f3 = f[3];
        FMA16(a0, w.x, f0, f1, f2, f3);
        FMA16(a1, w.y, f0, f1, f2, f3);
    }
    float m0 = -FLT_MAX, m1 = -FLT_MAX;
    #pragma unroll
    for (int i = 0; i < 8; i++) {
        float2 x = unpack2(a0[i]); m0 = fmaxf(m0, fmaxf(x.x, x.y));
        float2 y = unpack2(a1[i]); m1 = fmaxf(m1, fmaxf(y.x, y.y));
    }
    *reinterpret_cast<float2*>(&xout[((size_t)b*Nq + q)*C_HID + j0]) = make_float2(m0, m1);
}

// ---------------- up: 3-NN inverse-distance interp + cat + linear + relu ----------------
template<int C_XC, int C_PRV, int C_OUT>
__global__ void up_kernel(const float* __restrict__ xc, const float* __restrict__ prv,
                          const int* __restrict__ idx, const float* __restrict__ d2,
                          const float* __restrict__ Wd, const float* __restrict__ bias,
                          float* __restrict__ out, int Nq, int Nc) {
    constexpr int CIN = C_XC + C_PRV;
    constexpr int QT = 16;
    extern __shared__ float sm[];
    float* featT = sm;
    __shared__ float wsh[QT][3];
    __shared__ int   ish[QT][3];
    int b = blockIdx.y;
    int q0 = blockIdx.x * QT;
    if (threadIdx.x < QT) {
        int q = q0 + threadIdx.x;
        size_t base = ((size_t)b*Nq + q)*3;
        float w0 = 1.0f/(d2[base+0] + 1e-8f);
        float w1 = 1.0f/(d2[base+1] + 1e-8f);
        float w2 = 1.0f/(d2[base+2] + 1e-8f);
        float s = w0 + w1 + w2;
        wsh[threadIdx.x][0] = w0/s; wsh[threadIdx.x][1] = w1/s; wsh[threadIdx.x][2] = w2/s;
        ish[threadIdx.x][0] = idx[base+0]; ish[threadIdx.x][1] = idx[base+1]; ish[threadIdx.x][2] = idx[base+2];
    }
    __syncthreads();
    const float* xcb = xc + (size_t)b*Nc*C_XC;
    for (int e = threadIdx.x; e < CIN*QT; e += blockDim.x) {
        int d = e >> 4, qq = e & 15;
        float v;
        if (d < C_XC) {
            v = wsh[qq][0]*xcb[(size_t)ish[qq][0]*C_XC + d]
              + wsh[qq][1]*xcb[(size_t)ish[qq][1]*C_XC + d]
              + wsh[qq][2]*xcb[(size_t)ish[qq][2]*C_XC + d];
        } else {
            v = prv[((size_t)b*Nq + q0 + qq)*C_PRV + (d - C_XC)];
        }
        featT[e] = v;
    }
    __syncthreads();
    int j0 = 2*threadIdx.x;
    u64 a0[8], a1[8];
    {
        float2 bb = *reinterpret_cast<const float2*>(&bias[j0]);
        u64 p0 = pack2(bb.x, bb.x), p1 = pack2(bb.y, bb.y);
        #pragma unroll
        for (int i = 0; i < 8; i++) { a0[i] = p0; a1[i] = p1; }
    }
    #pragma unroll 2
    for (int d = 0; d < CIN; d++) {
        ulonglong2 w = *reinterpret_cast<const ulonglong2*>(Wd + 2*(d*C_OUT + j0));
        const ulonglong2* f = reinterpret_cast<const ulonglong2*>(featT + d*QT);
        ulonglong2 f0 = f[0], f1 = f[1], f2 = f[2], f3 = f[3];
        FMA16(a0, w.x, f0, f1, f2, f3);
        FMA16(a1, w.y, f0, f1, f2, f3);
    }
    size_t obase = ((size_t)b*Nq + q0)*C_OUT + j0;
    #pragma unroll
    for (int i = 0; i < 8; i++) {
        float2 x = unpack2(a0[i]), y = unpack2(a1[i]);
        *reinterpret_cast<float2*>(&out[obase + (size_t)(2*i+0)*C_OUT]) =
            make_float2(fmaxf(x.x,0.f), fmaxf(y.x,0.f));
        *reinterpret_cast<float2*>(&out[obase + (size_t)(2*i+1)*C_OUT]) =
            make_float2(fmaxf(x.y,0.f), fmaxf(y.y,0.f));
    }
}

// ---------------- fused: up2 + final MLP (QT=16, 64 threads) ----------------
__global__ void up2_final_kernel(const float* __restrict__ up1,
                                 const float* __restrict__ x0, const float* __restrict__ pos0,
                                 const int* __restrict__ idx, const float* __restrict__ d2,
                                 const float* __restrict__ u2Wd, const float* __restrict__ u2b,
                                 const float* __restrict__ fW1d, const float* __restrict__ fb1,
                                 const float* __restrict__ fW2d, const float* __restrict__ fb2,
                                 float* __restrict__ out) {
    constexpr int QT = 16;
    __shared__ float featT[134*QT];
    __shared__ float h1T[128*QT];
    __shared__ float wsh[QT][3];
    __shared__ int   ish[QT][3];
    int b = blockIdx.y;
    int q0 = blockIdx.x * QT;
    if (threadIdx.x < QT) {
        int q = q0 + threadIdx.x;
        size_t base = ((size_t)b*NN0 + q)*3;
        float w0 = 1.0f/(d2[base+0] + 1e-8f);
        float w1 = 1.0f/(d2[base+1] + 1e-8f);
        float w2 = 1.0f/(d2[base+2] + 1e-8f);
        float s = w0 + w1 + w2;
        wsh[threadIdx.x][0] = w0/s; wsh[threadIdx.x][1] = w1/s; wsh[threadIdx.x][2] = w2/s;
        ish[threadIdx.x][0] = idx[base+0]; ish[threadIdx.x][1] = idx[base+1]; ish[threadIdx.x][2] = idx[base+2];
    }
    __syncthreads();
    const float* xcb = up1 + (size_t)b*NN1*128;
    for (int e = threadIdx.x; e < 134*QT; e += 64) {
        int d = e >> 4, qq = e & 15;
        float v;
        if (d < 128) {
            v = wsh[qq][0]*xcb[(size_t)ish[qq][0]*128 + d]
              + wsh[qq][1]*xcb[(size_t)ish[qq][1]*128 + d]
              + wsh[qq][2]*xcb[(size_t)ish[qq][2]*128 + d];
        } else if (d < 131) {
            v = x0  [((size_t)b*NN0 + q0 + qq)*3 + (d-128)];
        } else {
            v = pos0[((size_t)b*NN0 + q0 + qq)*3 + (d-131)];
        }
        featT[e] = v;
    }
    __syncthreads();
    int j0 = 2*threadIdx.x;
    u64 a0[8], a1[8];

    {
        float2 bb = *reinterpret_cast<const float2*>(&u2b[j0]);
        u64 p0 = pack2(bb.x, bb.x), p1 = pack2(bb.y, bb.y);
        #pragma unroll
        for (int i = 0; i < 8; i++) { a0[i] = p0; a1[i] = p1; }
    }
    #pragma unroll 2
    for (int d = 0; d < 134; d++) {
        ulonglong2 w = *reinterpret_cast<const ulonglong2*>(u2Wd + 2*(d*128 + j0));
        const ulonglong2* f = reinterpret_cast<const ulonglong2*>(featT + d*QT);
        ulonglong2 f0 = f[0], f1 = f[1], f2 = f[2], f3 = f[3];
        FMA16(a0, w.x, f0, f1, f2, f3);
        FMA16(a1, w.y, f0, f1, f2, f3);
    }
    {
        float4* h0 = reinterpret_cast<float4*>(h1T + (size_t)j0*QT);
        float4* h1 = reinterpret_cast<float4*>(h1T + (size_t)(j0+1)*QT);
        #pragma unroll
        for (int i = 0; i < 4; i++) {
            float2 x0v = unpack2(a0[2*i]), x1v = unpack2(a0[2*i+1]);
            h0[i] = make_float4(fmaxf(x0v.x,0.f), fmaxf(x0v.y,0.f), fmaxf(x1v.x,0.f), fmaxf(x1v.y,0.f));
            float2 y0v = unpack2(a1[2*i]), y1v = unpack2(a1[2*i+1]);
            h1[i] = make_float4(fmaxf(y0v.x,0.f), fmaxf(y0v.y,0.f), fmaxf(y1v.x,0.f), fmaxf(y1v.y,0.f));
        }
    }
    __syncthreads();

    {
        float2 bb = *reinterpret_cast<const float2*>(&fb1[j0]);
        u64 p0 = pack2(bb.x, bb.x), p1 = pack2(bb.y, bb.y);
        #pragma unroll
        for (int i = 0; i < 8; i++) { a0[i] = p0; a1[i] = p1; }
    }
    #pragma unroll 2
    for (int d = 0; d < 128; d++) {
        ulonglong2 w = *reinterpret_cast<const ulonglong2*>(fW1d + 2*(d*128 + j0));
        const ulonglong2* f = reinterpret_cast<const ulonglong2*>(h1T + d*QT);
        ulonglong2 f0 = f[0], f1 = f[1], f2 = f[2], f3 = f[3];
        FMA16(a0, w.x, f0, f1, f2, f3);
        FMA16(a1, w.y, f0, f1, f2, f3);
    }
    __syncthreads();
    {
        float4* h0 = reinterpret_cast<float4*>(featT + (size_t)j0*QT);
        float4* h1 = reinterpret_cast<float4*>(featT + (size_t)(j0+1)*QT);
        #pragma unroll
        for (int i = 0; i < 4; i++) {
            float2 x0v = unpack2(a0[2*i]), x1v = unpack2(a0[2*i+1]);
            h0[i] = make_float4(fmaxf(x0v.x,0.f), fmaxf(x0v.y,0.f), fmaxf(x1v.x,0.f), fmaxf(x1v.y,0.f));
            float2 y0v = unpack2(a1[2*i]), y1v = unpack2(a1[2*i+1]);
            h1[i] = make_float4(fmaxf(y0v.x,0.f), fmaxf(y0v.y,0.f), fmaxf(y1v.x,0.f), fmaxf(y1v.y,0.f));
        }
    }
    __syncthreads();

    {
        float2 bb = *reinterpret_cast<const float2*>(&fb2[j0]);
        u64 p0 = pack2(bb.x, bb.x), p1 = pack2(bb.y, bb.y);
        #pragma unroll
        for (int i = 0; i < 8; i++) { a0[i] = p0; a1[i] = p1; }
    }
    #pragma unroll 2
    for (int d = 0; d < 128; d++) {
        ulonglong2 w = *reinterpret_cast<const ulonglong2*>(fW2d + 2*(d*128 + j0));
        const ulonglong2* f = reinterpret_cast<const ulonglong2*>(featT + d*QT);
        ulonglong2 f0 = f[0], f1 = f[1], f2 = f[2], f3 = f[3];
        FMA16(a0, w.x, f0, f1, f2, f3);
        FMA16(a1, w.y, f0, f1, f2, f3);
    }
    size_t obase = ((size_t)b*NN0 + q0)*128 + j0;
    #pragma unroll
    for (int i = 0; i < 8; i++) {
        float2 x = unpack2(a0[i]), y = unpack2(a1[i]);
        *reinterpret_cast<float2*>(&out[obase + (size_t)(2*i+0)*128]) = make_float2(x.x, y.x);
        *reinterpret_cast<float2*>(&out[obase + (size_t)(2*i+1)*128]) = make_float2(x.y, y.y);
    }
}

// ---------------- host launch ----------------
extern "C" void kernel_launch(void* const* d_in, const int* in_sizes, int n_in,
                              void* d_out, int out_size) {
    const float* x    = (const float*)d_in[0];
    const float* pos  = (const float*)d_in[1];
    const float* d0W1 = (const float*)d_in[2];
    const float* d0b1 = (const float*)d_in[3];
    const float* d0W2 = (const float*)d_in[4];
    const float* d0b2 = (const float*)d_in[5];
    const float* d1W1 = (const float*)d_in[6];
    const float* d1b1 = (const float*)d_in[7];
    const float* d1W2 = (const float*)d_in[8];
    const float* d1b2 = (const float*)d_in[9];
    const float* d2W1 = (const float*)d_in[10];
    const float* d2b1 = (const float*)d_in[11];
    const float* d2W2 = (const float*)d_in[12];
    const float* d2b2 = (const float*)d_in[13];
    const float* u0W  = (const float*)d_in[14];
    const float* u0b  = (const float*)d_in[15];
    const float* u1W  = (const float*)d_in[16];
    const float* u1b  = (const float*)d_in[17];
    const float* u2W  = (const float*)d_in[18];
    const float* u2b  = (const float*)d_in[19];
    const float* fW1  = (const float*)d_in[20];
    const float* fb1  = (const float*)d_in[21];
    const float* fW2  = (const float*)d_in[22];
    const float* fb2  = (const float*)d_in[23];
    float* out = (float*)d_out;

    int *idx0, *idx1, *idx2, *uidx0, *uidx1, *uidx2;
    float *ud20, *ud21, *ud22, *x1, *x2, *x3, *up0, *up1, *wd;
    float4* pos4;
    cudaGetSymbolAddress((void**)&idx0,  g_idx0);
    cudaGetSymbolAddress((void**)&idx1,  g_idx1);
    cudaGetSymbolAddress((void**)&idx2,  g_idx2);
    cudaGetSymbolAddress((void**)&uidx0, g_uidx0);
    cudaGetSymbolAddress((void**)&uidx1, g_uidx1);
    cudaGetSymbolAddress((void**)&uidx2, g_uidx2);
    cudaGetSymbolAddress((void**)&ud20,  g_ud20);
    cudaGetSymbolAddress((void**)&ud21,  g_ud21);
    cudaGetSymbolAddress((void**)&ud22,  g_ud22);
    cudaGetSymbolAddress((void**)&x1,    g_x1);
    cudaGetSymbolAddress((void**)&x2,    g_x2);
    cudaGetSymbolAddress((void**)&x3,    g_x3);
    cudaGetSymbolAddress((void**)&up0,   g_up0);
    cudaGetSymbolAddress((void**)&up1,   g_up1);
    cudaGetSymbolAddress((void**)&wd,    g_wdup);
    cudaGetSymbolAddress((void**)&pos4,  g_pos4);

    const float* d0W1d = wd + 2*OFF_D0W1;
    const float* d0W2d = wd + 2*OFF_D0W2;
    const float* d1W1d = wd + 2*OFF_D1W1;
    const float* d1W2d = wd + 2*OFF_D1W2;
    const float* d2W1d = wd + 2*OFF_D2W1;
    const float* d2W2d = wd + 2*OFF_D2W2;
    const float* u0Wd  = wd + 2*OFF_U0W;
    const float* u1Wd  = wd + 2*OFF_U1W;
    const float* u2Wd  = wd + 2*OFF_U2W;
    const float* fW1d  = wd + 2*OFF_FW1;
    const float* fW2d  = wd + 2*OFF_FW2;

    cudaFuncSetAttribute((const void*)down_kernel<256,512>,
                         cudaFuncAttributeMaxDynamicSharedMemorySize, 56*1024);
    cudaFuncSetAttribute((const void*)up_kernel<512,256,256>,
                         cudaFuncAttributeMaxDynamicSharedMemorySize, 50*1024);

    // ---- preps ----
    prep_pos4_kernel<<<(Bz*NN0)/256, 256>>>(pos, pos4);
    dup_weights_kernel<<<(W_TOTAL+255)/256, 256>>>(
        d0W1,d0W2,d1W1,d1W2,d2W1,d2W2,u0W,u1W,u2W,fW1,fW2, wd);

    // ---- down 0: knn(2048 q, 8192 refs) + MLP ----
    knn16_kernel<32,8><<<dim3(NN1,Bz), 256>>>(pos4, NN1, idx0);
    down_kernel<3,128><<<dim3(NN1,Bz), 64, (6*16 + 128*16)*sizeof(float)>>>(
        x, pos, idx0, d0W1d,d0b1, d0W2d,d0b2, x1, NN1, NN0*3);
    // ---- down 1: knn(512 q, 2048 refs) + MLP ----
    knn16_kernel<8,8><<<dim3(NN2,Bz), 256>>>(pos4, NN2, idx1);
    down_kernel<128,256><<<dim3(NN2,Bz), 128, (131*16 + 256*16)*sizeof(float)>>>(
        x1, pos, idx1, d1W1d,d1b1, d1W2d,d1b2, x2, NN2, NN1*128);
    // ---- down 2: knn(128 q, 512 refs) + MLP ----
    knn16_kernel<2,8><<<dim3(NN3,Bz), 256>>>(pos4, NN3, idx2);
    down_kernel<256,512><<<dim3(NN3,Bz), 256, (259*16 + 512*16)*sizeof(float)>>>(
        x2, pos, idx2, d2W1d,d2b1, d2W2d,d2b2, x3, NN3, NN2*256);
    // ---- up 0: knn(512 q, 128 refs) + interp/MLP ----
    knn3_kernel<4><<<dim3(NN2/8,Bz), 256>>>(pos4, NN2, uidx0, ud20);
    up_kernel<512,256,256><<<dim3(NN2/16,Bz), 128, 768*16*sizeof(float)>>>(
        x3, x2, uidx0, ud20, u0Wd, u0b, up0, NN2, NN3);
    // ---- up 1: knn(2048 q, 512 refs) + interp/MLP ----
    knn3_kernel<16><<<dim3(NN1/8,Bz), 256>>>(pos4, NN1, uidx1, ud21);
    up_kernel<256,128,128><<<dim3(NN1/16,Bz), 64, 384*16*sizeof(float)>>>(
        up0, x1, uidx1, ud21, u1Wd, u1b, up1, NN1, NN2);
    // ---- up 2 + final MLP: knn(8192 q, 2048 refs; warp-per-query) + fused ----
    knn3_kernel<64><<<dim3(NN0/8,Bz), 256>>>(pos4, NN0, uidx2, ud22);
    up2_final_kernel<<<dim3(NN0/16,Bz), 64>>>(up1, x, pos, uidx2, ud22,
                                              u2Wd,u2b, fW1d,fb1, fW2d,fb2, out);
    // ---- second tuple element: pos0 passthrough ----
    if (out_size >= Bz*NN0*128 + Bz*NN0*3) {
        cudaMemcpyAsync(out + (size_t)Bz*NN0*128, pos,
                        (size_t)Bz*NN0*3*sizeof(float), cudaMemcpyDeviceToDevice);
    }
}

// round 14
// speedup vs baseline: 1.1201x; 1.0298x over previous
#include <cuda_runtime.h>
#include <cfloat>
#include <cstdint>

#define Bz 4
#define NN0 8192
#define NN1 2048
#define NN2 512
#define NN3 128

typedef unsigned long long u64;

__device__ __forceinline__ u64 pack2(float x, float y) {
    u64 r; asm("mov.b64 %0, {%1, %2};" : "=l"(r) : "f"(x), "f"(y)); return r;
}
__device__ __forceinline__ float2 unpack2(u64 v) {
    float2 r; asm("mov.b64 {%0, %1}, %2;" : "=f"(r.x), "=f"(r.y) : "l"(v)); return r;
}
__device__ __forceinline__ u64 ffma2(u64 a, u64 b, u64 c) {
    u64 d; asm("fma.rn.f32x2 %0, %1, %2, %3;" : "=l"(d) : "l"(a), "l"(b), "l"(c)); return d;
}
__device__ __forceinline__ unsigned ordf(float f) {
    unsigned b = __float_as_uint(f);
    return b ^ (((unsigned)((int)b >> 31)) | 0x80000000u);
}
__device__ __forceinline__ float unordf(unsigned m) {
    unsigned b = m ^ ((m & 0x80000000u) ? 0x80000000u : 0xffffffffu);
    return __uint_as_float(b);
}

#define INS3(u, si) do { \
    bool p1 = (u) < m1v; \
    unsigned c1v = p1 ? m1v : (u);  int c1s = p1 ? m1s : (si); \
    m1v = p1 ? (u) : m1v;           m1s = p1 ? (si) : m1s; \
    bool p2 = c1v < m2v; \
    unsigned c2v = p2 ? m2v : c1v;  int c2s = p2 ? m2s : c1s; \
    m2v = p2 ? c1v : m2v;           m2s = p2 ? c1s : m2s; \
    bool p3 = c2v < m3v; \
    m3v = p3 ? c2v : m3v;           m3s = p3 ? c2s : m3s; \
} while(0)

#define FMA16(acc, w, F0, F1, F2, F3) do { \
    acc[0]=ffma2(F0.x,(w),acc[0]); acc[1]=ffma2(F0.y,(w),acc[1]); \
    acc[2]=ffma2(F1.x,(w),acc[2]); acc[3]=ffma2(F1.y,(w),acc[3]); \
    acc[4]=ffma2(F2.x,(w),acc[4]); acc[5]=ffma2(F2.y,(w),acc[5]); \
    acc[6]=ffma2(F3.x,(w),acc[6]); acc[7]=ffma2(F3.y,(w),acc[7]); \
} while(0)

// ---------------- scratch (allocation-free) ----------------
__device__ int   g_idx0[Bz*NN1*16];
__device__ int   g_idx1[Bz*NN2*16];
__device__ int   g_idx2[Bz*NN3*16];
__device__ int   g_uidx0[Bz*NN2*3];
__device__ float g_ud20 [Bz*NN2*3];
__device__ int   g_uidx1[Bz*NN1*3];
__device__ float g_ud21 [Bz*NN1*3];
__device__ int   g_uidx2[Bz*NN0*3];
__device__ float g_ud22 [Bz*NN0*3];
__device__ float g_x1 [Bz*NN1*128];
__device__ float g_x2 [Bz*NN2*256];
__device__ float g_x3 [Bz*NN3*512];
__device__ float g_up0[Bz*NN2*256];
__device__ float g_up1[Bz*NN1*128];
__device__ __align__(16) float g_wdup[2*806656];
__device__ __align__(16) float4 g_pos4[Bz*NN0];

#define OFF_D0W1 0
#define OFF_D0W2 768
#define OFF_D1W1 17152
#define OFF_D1W2 50688
#define OFF_D2W1 116224
#define OFF_D2W2 248832
#define OFF_U0W  510976
#define OFF_U1W  707584
#define OFF_U2W  756736
#define OFF_FW1  773888
#define OFF_FW2  790272
#define W_TOTAL  806656

// ---------------- prep: weight duplication ----------------
__global__ void dup_weights_kernel(const float* __restrict__ s0, const float* __restrict__ s1,
                                   const float* __restrict__ s2, const float* __restrict__ s3,
                                   const float* __restrict__ s4, const float* __restrict__ s5,
                                   const float* __restrict__ s6, const float* __restrict__ s7,
                                   const float* __restrict__ s8, const float* __restrict__ s9,
                                   const float* __restrict__ s10, float* __restrict__ dst) {
    int gid = blockIdx.x*256 + threadIdx.x;
    if (gid >= W_TOTAL) return;
    const int offs[11] = {OFF_D0W1,OFF_D0W2,OFF_D1W1,OFF_D1W2,OFF_D2W1,OFF_D2W2,
                          OFF_U0W,OFF_U1W,OFF_U2W,OFF_FW1,OFF_FW2};
    const float* srcs[11] = {s0,s1,s2,s3,s4,s5,s6,s7,s8,s9,s10};
    int seg = 0;
    #pragma unroll
    for (int i = 1; i < 11; i++) seg = (gid >= offs[i]) ? i : seg;
    float v = srcs[seg][gid - offs[seg]];
    reinterpret_cast<float2*>(dst)[gid] = make_float2(v, v);
}

// ---------------- prep: pos -> (x,y,z,|r|^2) ----------------
__global__ void prep_pos4_kernel(const float* __restrict__ pos, float4* __restrict__ out) {
    int i = blockIdx.x*256 + threadIdx.x;
    float x = pos[3*i+0], y = pos[3*i+1], z = pos[3*i+2];
    float rr = x*x + y*y + z*z;
    out[i] = make_float4(x, y, z, rr);
}

// ---------------- KNN K=16 (validated: CNT=32, NWARP=8) ----------------
template<int CNT, int NWARP>
__global__ void knn16_kernel(const float4* __restrict__ pos4, int Nq, int* __restrict__ oidx) {
    __shared__ u64 skey[NWARP*16];
    int b = blockIdx.y, q = blockIdx.x;
    int lane = threadIdx.x & 31, w = threadIdx.x >> 5;
    const float4* rp = pos4 + (size_t)b*NN0;
    float4 qp = rp[q];
    float qx = qp.x, qy = qp.y, qz = qp.z, qq = qp.w;
    int base = w*CNT*32;

    unsigned ud[CNT];
    unsigned m1v = 0xffffffffu, m2v = 0xffffffffu, m3v = 0xffffffffu;
    int m1s = 0, m2s = 0, m3s = 0;
    #pragma unroll
    for (int i = 0; i < CNT; i++) {
        float4 r4 = rp[base + i*32 + lane];
        float dt = qx*r4.x + qy*r4.y + qz*r4.z;
        float dv = qq + r4.w - 2.0f*dt;
        unsigned u = ordf(dv);
        ud[i] = u;
        INS3(u, i);
    }
    for (int s = 0; s < 16; s++) {
        unsigned mh = __reduce_min_sync(0xffffffffu, m1v);
        unsigned cand = (m1v == mh) ? (unsigned)(m1s*32 + lane) : 0xffffffffu;
        unsigned ml = __reduce_min_sync(0xffffffffu, cand);
        if (lane == 0) skey[w*16 + s] = ((u64)mh << 32) | (unsigned)(base + (int)ml);
        if (cand == ml && m1v == mh) {
            unsigned thr = m1v;
            m1v = m2v; m1s = m2s;
            m2v = m3v; m2s = m3s;
            m3v = 0xffffffffu;
            if (m1v == 0xffffffffu) {   // exhausted buffer: exact rebuild above threshold
                m2v = 0xffffffffu; m3v = 0xffffffffu;
                #pragma unroll
                for (int i = 0; i < CNT; i++) {
                    unsigned u = ud[i];
                    if (u > thr) { INS3(u, i); }
                }
            }
        }
    }
    __syncthreads();
    if (w == 0) {
        u64 head = ~0ull; int ptr = 0;
        if (lane < NWARP) head = skey[lane*16];
        size_t obase = ((size_t)b*Nq + q)*16;
        for (int s = 0; s < 16; s++) {
            unsigned hi = (unsigned)(head >> 32);
            unsigned mh = __reduce_min_sync(0xffffffffu, hi);
            unsigned lo = (hi == mh) ? (unsigned)head : 0xffffffffu;
            unsigned ml = __reduce_min_sync(0xffffffffu, lo);
            if (lane == 0) oidx[obase + s] = (int)ml;
            u64 best = ((u64)mh << 32) | ml;
            if (head == best) {
                ptr++;
                head = (ptr < 16) ? skey[lane*16 + ptr] : ~0ull;
            }
        }
    }
}

// ---------------- KNN K=3, warp variant (validated) ----------------
template<int CNT>
__global__ void knn3_kernel(const float4* __restrict__ pos4, int Nq,
                            int* __restrict__ oidx, float* __restrict__ od2) {
    int b = blockIdx.y;
    int lane = threadIdx.x & 31;
    int q = blockIdx.x*8 + (threadIdx.x >> 5);
    const float4* rp = pos4 + (size_t)b*NN0;
    float4 qp = rp[q];
    float qx = qp.x, qy = qp.y, qz = qp.z, qq = qp.w;

    unsigned m1v = 0xffffffffu, m2v = 0xffffffffu, m3v = 0xffffffffu;
    int m1s = 0, m2s = 0, m3s = 0;
    #pragma unroll 8
    for (int i = 0; i < CNT; i++) {
        float4 r4 = rp[i*32 + lane];
        float dt = qx*r4.x + qy*r4.y + qz*r4.z;
        float dv = qq + r4.w - 2.0f*dt;
        unsigned u = ordf(dv);
        INS3(u, i);
    }
    size_t obase = ((size_t)b*Nq + q)*3;
    #pragma unroll
    for (int s = 0; s < 3; s++) {
        unsigned mh = __reduce_min_sync(0xffffffffu, m1v);
        unsigned cand = (m1v == mh) ? (unsigned)(m1s*32 + lane) : 0xffffffffu;
        unsigned ml = __reduce_min_sync(0xffffffffu, cand);
        if (lane == 0) {
            oidx[obase + s] = (int)ml;
            od2[obase + s]  = fmaxf(unordf(mh), 0.0f);
        }
        if (cand == ml && m1v == mh) {
            m1v = m2v; m1s = m2s;
            m2v = m3v; m2s = m3s;
            m3v = 0xffffffffu;
        }
    }
}

// ---------------- down: gather + 2-layer MLP + max over 16 (one center, j-block=2) ----------------
template<int C_PREV, int C_HID>
__global__ void down_kernel(const float* __restrict__ xprev, const float* __restrict__ pos,
                            const int* __restrict__ idx,
                            const float* __restrict__ W1d, const float* __restrict__ b1,
                            const float* __restrict__ W2d, const float* __restrict__ b2,
                            float* __restrict__ xout, int Nq, int xbs) {
    constexpr int CIN = 3 + C_PREV;
    extern __shared__ float sm[];
    float* featT = sm;               // CIN*16
    float* hT    = sm + CIN*16;      // C_HID*16
    __shared__ int nbs[16];
    int b = blockIdx.y, q = blockIdx.x;
    if (threadIdx.x < 16) nbs[threadIdx.x] = idx[((size_t)b*Nq + q)*16 + threadIdx.x];
    __syncthreads();
    const float* rp = pos + (size_t)b*NN0*3;
    float cx = rp[3*q+0], cy = rp[3*q+1], cz = rp[3*q+2];
    const float* xp = xprev + (size_t)b*xbs;
    for (int e = threadIdx.x; e < 16*CIN; e += blockDim.x) {
        int d = e >> 4, k = e & 15;
        int nb = nbs[k];
        float v;
        if      (d == 0) v = rp[3*nb+0] - cx;
        else if (d == 1) v = rp[3*nb+1] - cy;
        else if (d == 2) v = rp[3*nb+2] - cz;
        else             v = xp[(size_t)nb*C_PREV + (d-3)];
        featT[d*16 + k] = v;
    }
    __syncthreads();
    int j0 = 2*threadIdx.x;
    u64 a0[8], a1[8];
    {
        float2 bb = *reinterpret_cast<const float2*>(&b1[j0]);
        u64 p0 = pack2(bb.x, bb.x), p1 = pack2(bb.y, bb.y);
        #pragma unroll
        for (int i = 0; i < 8; i++) { a0[i] = p0; a1[i] = p1; }
    }
    #pragma unroll 2
    for (int d = 0; d < CIN; d++) {
        ulonglong2 w = *reinterpret_cast<const ulonglong2*>(W1d + 2*(d*C_HID + j0));
        const ulonglong2* f = reinterpret_cast<const ulonglong2*>(featT + d*16);
        ulonglong2 f0 = f[0], f1 = f[1], f2 = f[2], f3 = f[3];
        FMA16(a0, w.x, f0, f1, f2, f3);
        FMA16(a1, w.y, f0, f1, f2, f3);
    }
    {
        float4* h0 = reinterpret_cast<float4*>(hT + (size_t)j0*16);
        float4* h1 = reinterpret_cast<float4*>(hT + (size_t)(j0+1)*16);
        #pragma unroll
        for (int i = 0; i < 4; i++) {
            float2 x0 = unpack2(a0[2*i]), x1 = unpack2(a0[2*i+1]);
            h0[i] = make_float4(fmaxf(x0.x,0.f), fmaxf(x0.y,0.f), fmaxf(x1.x,0.f), fmaxf(x1.y,0.f));
            float2 y0 = unpack2(a1[2*i]), y1 = unpack2(a1[2*i+1]);
            h1[i] = make_float4(fmaxf(y0.x,0.f), fmaxf(y0.y,0.f), fmaxf(y1.x,0.f), fmaxf(y1.y,0.f));
        }
    }
    __syncthreads();
    {
        float2 bb = *reinterpret_cast<const float2*>(&b2[j0]);
        u64 p0 = pack2(bb.x, bb.x), p1 = pack2(bb.y, bb.y);
        #pragma unroll
        for (int i = 0; i < 8; i++) { a0[i] = p0; a1[i] = p1; }
    }
    #pragma unroll 2
    for (int d = 0; d < C_HID; d++) {
        ulonglong2 w = *reinterpret_cast<const ulonglong2*>(W2d + 2*(d*C_HID + j0));
        const ulonglong2* f = reinterpret_cast<const ulonglong2*>(hT + d*16);
        ulonglong2 f0 = f[0], f1 = f[1], f2 = f[2], f3 = f[3];
        FMA16(a0, w.x, f0, f1, f2, f3);
        FMA16(a1, w.y, f0, f1, f2, f3);
    }
    float m0 = -FLT_MAX, m1 = -FLT_MAX;
    #pragma unroll
    for (int i = 0; i < 8; i++) {
        float2 x = unpack2(a0[i]); m0 = fmaxf(m0, fmaxf(x.x, x.y));
        float2 y = unpack2(a1[i]); m1 = fmaxf(m1, fmaxf(y.x, y.y));
    }
    *reinterpret_cast<float2*>(&xout[((size_t)b*Nq + q)*C_HID + j0]) = make_float2(m0, m1);
}

// ---------------- up: 3-NN inverse-distance interp + cat + linear + relu ----------------
template<int C_XC, int C_PRV, int C_OUT>
__global__ void up_kernel(const float* __restrict__ xc, const float* __restrict__ prv,
                          const int* __restrict__ idx, const float* __restrict__ d2,
                          const float* __restrict__ Wd, const float* __restrict__ bias,
                          float* __restrict__ out, int Nq, int Nc) {
    constexpr int CIN = C_XC + C_PRV;
    constexpr int QT = 16;
    extern __shared__ float sm[];
    float* featT = sm;
    __shared__ float wsh[QT][3];
    __shared__ int   ish[QT][3];
    int b = blockIdx.y;
    int q0 = blockIdx.x * QT;
    if (threadIdx.x < QT) {
        int q = q0 + threadIdx.x;
        size_t base = ((size_t)b*Nq + q)*3;
        float w0 = 1.0f/(d2[base+0] + 1e-8f);
        float w1 = 1.0f/(d2[base+1] + 1e-8f);
        float w2 = 1.0f/(d2[base+2] + 1e-8f);
        float s = w0 + w1 + w2;
        wsh[threadIdx.x][0] = w0/s; wsh[threadIdx.x][1] = w1/s; wsh[threadIdx.x][2] = w2/s;
        ish[threadIdx.x][0] = idx[base+0]; ish[threadIdx.x][1] = idx[base+1]; ish[threadIdx.x][2] = idx[base+2];
    }
    __syncthreads();
    const float* xcb = xc + (size_t)b*Nc*C_XC;
    for (int e = threadIdx.x; e < CIN*QT; e += blockDim.x) {
        int d = e >> 4, qq = e & 15;
        float v;
        if (d < C_XC) {
            v = wsh[qq][0]*xcb[(size_t)ish[qq][0]*C_XC + d]
              + wsh[qq][1]*xcb[(size_t)ish[qq][1]*C_XC + d]
              + wsh[qq][2]*xcb[(size_t)ish[qq][2]*C_XC + d];
        } else {
            v = prv[((size_t)b*Nq + q0 + qq)*C_PRV + (d - C_XC)];
        }
        featT[e] = v;
    }
    __syncthreads();
    int j0 = 2*threadIdx.x;
    u64 a0[8], a1[8];
    {
        float2 bb = *reinterpret_cast<const float2*>(&bias[j0]);
        u64 p0 = pack2(bb.x, bb.x), p1 = pack2(bb.y, bb.y);
        #pragma unroll
        for (int i = 0; i < 8; i++) { a0[i] = p0; a1[i] = p1; }
    }
    #pragma unroll 2
    for (int d = 0; d < CIN; d++) {
        ulonglong2 w = *reinterpret_cast<const ulonglong2*>(Wd + 2*(d*C_OUT + j0));
        const ulonglong2* f = reinterpret_cast<const ulonglong2*>(featT + d*QT);
        ulonglong2 f0 = f[0], f1 = f[1], f2 = f[2], f3 = f[3];
        FMA16(a0, w.x, f0, f1, f2, f3);
        FMA16(a1, w.y, f0, f1, f2, f3);
    }
    size_t obase = ((size_t)b*Nq + q0)*C_OUT + j0;
    #pragma unroll
    for (int i = 0; i < 8; i++) {
        float2 x = unpack2(a0[i]), y = unpack2(a1[i]);
        *reinterpret_cast<float2*>(&out[obase + (size_t)(2*i+0)*C_OUT]) =
            make_float2(fmaxf(x.x,0.f), fmaxf(y.x,0.f));
        *reinterpret_cast<float2*>(&out[obase + (size_t)(2*i+1)*C_OUT]) =
            make_float2(fmaxf(x.y,0.f), fmaxf(y.y,0.f));
    }
}

// ---------------- fused: up2 + final MLP (QT=16, 64 threads) ----------------
__global__ void up2_final_kernel(const float* __restrict__ up1,
                                 const float* __restrict__ x0, const float* __restrict__ pos0,
                                 const int* __restrict__ idx, const float* __restrict__ d2,
                                 const float* __restrict__ u2Wd, const float* __restrict__ u2b,
                                 const float* __restrict__ fW1d, const float* __restrict__ fb1,
                                 const float* __restrict__ fW2d, const float* __restrict__ fb2,
                                 float* __restrict__ out) {
    constexpr int QT = 16;
    __shared__ float featT[134*QT];
    __shared__ float h1T[128*QT];
    __shared__ float wsh[QT][3];
    __shared__ int   ish[QT][3];
    int b = blockIdx.y;
    int q0 = blockIdx.x * QT;
    if (threadIdx.x < QT) {
        int q = q0 + threadIdx.x;
        size_t base = ((size_t)b*NN0 + q)*3;
        float w0 = 1.0f/(d2[base+0] + 1e-8f);
        float w1 = 1.0f/(d2[base+1] + 1e-8f);
        float w2 = 1.0f/(d2[base+2] + 1e-8f);
        float s = w0 + w1 + w2;
        wsh[threadIdx.x][0] = w0/s; wsh[threadIdx.x][1] = w1/s; wsh[threadIdx.x][2] = w2/s;
        ish[threadIdx.x][0] = idx[base+0]; ish[threadIdx.x][1] = idx[base+1]; ish[threadIdx.x][2] = idx[base+2];
    }
    __syncthreads();
    const float* xcb = up1 + (size_t)b*NN1*128;
    for (int e = threadIdx.x; e < 134*QT; e += 64) {
        int d = e >> 4, qq = e & 15;
        float v;
        if (d < 128) {
            v = wsh[qq][0]*xcb[(size_t)ish[qq][0]*128 + d]
              + wsh[qq][1]*xcb[(size_t)ish[qq][1]*128 + d]
              + wsh[qq][2]*xcb[(size_t)ish[qq][2]*128 + d];
        } else if (d < 131) {
            v = x0  [((size_t)b*NN0 + q0 + qq)*3 + (d-128)];
        } else {
            v = pos0[((size_t)b*NN0 + q0 + qq)*3 + (d-131)];
        }
        featT[e] = v;
    }
    __syncthreads();
    int j0 = 2*threadIdx.x;
    u64 a0[8], a1[8];

    {
        float2 bb = *reinterpret_cast<const float2*>(&u2b[j0]);
        u64 p0 = pack2(bb.x, bb.x), p1 = pack2(bb.y, bb.y);
        #pragma unroll
        for (int i = 0; i < 8; i++) { a0[i] = p0; a1[i] = p1; }
    }
    #pragma unroll 2
    for (int d = 0; d < 134; d++) {
        ulonglong2 w = *reinterpret_cast<const ulonglong2*>(u2Wd + 2*(d*128 + j0));
        const ulonglong2* f = reinterpret_cast<const ulonglong2*>(featT + d*QT);
        ulonglong2 f0 = f[0], f1 = f[1], f2 = f[2], f3 = f[3];
        FMA16(a0, w.x, f0, f1, f2, f3);
        FMA16(a1, w.y, f0, f1, f2, f3);
    }
    {
        float4* h0 = reinterpret_cast<float4*>(h1T + (size_t)j0*QT);
        float4* h1 = reinterpret_cast<float4*>(h1T + (size_t)(j0+1)*QT);
        #pragma unroll
        for (int i = 0; i < 4; i++) {
            float2 x0v = unpack2(a0[2*i]), x1v = unpack2(a0[2*i+1]);
            h0[i] = make_float4(fmaxf(x0v.x,0.f), fmaxf(x0v.y,0.f), fmaxf(x1v.x,0.f), fmaxf(x1v.y,0.f));
            float2 y0v = unpack2(a1[2*i]), y1v = unpack2(a1[2*i+1]);
            h1[i] = make_float4(fmaxf(y0v.x,0.f), fmaxf(y0v.y,0.f), fmaxf(y1v.x,0.f), fmaxf(y1v.y,0.f));
        }
    }
    __syncthreads();

    {
        float2 bb = *reinterpret_cast<const float2*>(&fb1[j0]);
        u64 p0 = pack2(bb.x, bb.x), p1 = pack2(bb.y, bb.y);
        #pragma unroll
        for (int i = 0; i < 8; i++) { a0[i] = p0; a1[i] = p1; }
    }
    #pragma unroll 2
    for (int d = 0; d < 128; d++) {
        ulonglong2 w = *reinterpret_cast<const ulonglong2*>(fW1d + 2*(d*128 + j0));
        const ulonglong2* f = reinterpret_cast<const ulonglong2*>(h1T + d*QT);
        ulonglong2 f0 = f[0], f1 = f[1], f2 = f[2], f3 = f[3];
        FMA16(a0, w.x, f0, f1, f2, f3);
        FMA16(a1, w.y, f0, f1, f2, f3);
    }
    __syncthreads();
    {
        float4* h0 = reinterpret_cast<float4*>(featT + (size_t)j0*QT);
        float4* h1 = reinterpret_cast<float4*>(featT + (size_t)(j0+1)*QT);
        #pragma unroll
        for (int i = 0; i < 4; i++) {
            float2 x0v = unpack2(a0[2*i]), x1v = unpack2(a0[2*i+1]);
            h0[i] = make_float4(fmaxf(x0v.x,0.f), fmaxf(x0v.y,0.f), fmaxf(x1v.x,0.f), fmaxf(x1v.y,0.f));
            float2 y0v = unpack2(a1[2*i]), y1v = unpack2(a1[2*i+1]);
            h1[i] = make_float4(fmaxf(y0v.x,0.f), fmaxf(y0v.y,0.f), fmaxf(y1v.x,0.f), fmaxf(y1v.y,0.f));
        }
    }
    __syncthreads();

    {
        float2 bb = *reinterpret_cast<const float2*>(&fb2[j0]);
        u64 p0 = pack2(bb.x, bb.x), p1 = pack2(bb.y, bb.y);
        #pragma unroll
        for (int i = 0; i < 8; i++) { a0[i] = p0; a1[i] = p1; }
    }
    #pragma unroll 2
    for (int d = 0; d < 128; d++) {
        ulonglong2 w = *reinterpret_cast<const ulonglong2*>(fW2d + 2*(d*128 + j0));
        const ulonglong2* f = reinterpret_cast<const ulonglong2*>(featT + d*QT);
        ulonglong2 f0 = f[0], f1 = f[1], f2 = f[2], f3 = f[3];
        FMA16(a0, w.x, f0, f1, f2, f3);
        FMA16(a1, w.y, f0, f1, f2, f3);
    }
    size_t obase = ((size_t)b*NN0 + q0)*128 + j0;
    #pragma unroll
    for (int i = 0; i < 8; i++) {
        float2 x = unpack2(a0[i]), y = unpack2(a1[i]);
        *reinterpret_cast<float2*>(&out[obase + (size_t)(2*i+0)*128]) = make_float2(x.x, y.x);
        *reinterpret_cast<float2*>(&out[obase + (size_t)(2*i+1)*128]) = make_float2(x.y, y.y);
    }
}

// ---------------- host launch ----------------
extern "C" void kernel_launch(void* const* d_in, const int* in_sizes, int n_in,
                              void* d_out, int out_size) {
    const float* x    = (const float*)d_in[0];
    const float* pos  = (const float*)d_in[1];
    const float* d0W1 = (const float*)d_in[2];
    const float* d0b1 = (const float*)d_in[3];
    const float* d0W2 = (const float*)d_in[4];
    const float* d0b2 = (const float*)d_in[5];
    const float* d1W1 = (const float*)d_in[6];
    const float* d1b1 = (const float*)d_in[7];
    const float* d1W2 = (const float*)d_in[8];
    const float* d1b2 = (const float*)d_in[9];
    const float* d2W1 = (const float*)d_in[10];
    const float* d2b1 = (const float*)d_in[11];
    const float* d2W2 = (const float*)d_in[12];
    const float* d2b2 = (const float*)d_in[13];
    const float* u0W  = (const float*)d_in[14];
    const float* u0b  = (const float*)d_in[15];
    const float* u1W  = (const float*)d_in[16];
    const float* u1b  = (const float*)d_in[17];
    const float* u2W  = (const float*)d_in[18];
    const float* u2b  = (const float*)d_in[19];
    const float* fW1  = (const float*)d_in[20];
    const float* fb1  = (const float*)d_in[21];
    const float* fW2  = (const float*)d_in[22];
    const float* fb2  = (const float*)d_in[23];
    float* out = (float*)d_out;

    int *idx0, *idx1, *idx2, *uidx0, *uidx1, *uidx2;
    float *ud20, *ud21, *ud22, *x1, *x2, *x3, *up0, *up1, *wd;
    float4* pos4;
    cudaGetSymbolAddress((void**)&idx0,  g_idx0);
    cudaGetSymbolAddress((void**)&idx1,  g_idx1);
    cudaGetSymbolAddress((void**)&idx2,  g_idx2);
    cudaGetSymbolAddress((void**)&uidx0, g_uidx0);
    cudaGetSymbolAddress((void**)&uidx1, g_uidx1);
    cudaGetSymbolAddress((void**)&uidx2, g_uidx2);
    cudaGetSymbolAddress((void**)&ud20,  g_ud20);
    cudaGetSymbolAddress((void**)&ud21,  g_ud21);
    cudaGetSymbolAddress((void**)&ud22,  g_ud22);
    cudaGetSymbolAddress((void**)&x1,    g_x1);
    cudaGetSymbolAddress((void**)&x2,    g_x2);
    cudaGetSymbolAddress((void**)&x3,    g_x3);
    cudaGetSymbolAddress((void**)&up0,   g_up0);
    cudaGetSymbolAddress((void**)&up1,   g_up1);
    cudaGetSymbolAddress((void**)&wd,    g_wdup);
    cudaGetSymbolAddress((void**)&pos4,  g_pos4);

    const float* d0W1d = wd + 2*OFF_D0W1;
    const float* d0W2d = wd + 2*OFF_D0W2;
    const float* d1W1d = wd + 2*OFF_D1W1;
    const float* d1W2d = wd + 2*OFF_D1W2;
    const float* d2W1d = wd + 2*OFF_D2W1;
    const float* d2W2d = wd + 2*OFF_D2W2;
    const float* u0Wd  = wd + 2*OFF_U0W;
    const float* u1Wd  = wd + 2*OFF_U1W;
    const float* u2Wd  = wd + 2*OFF_U2W;
    const float* fW1d  = wd + 2*OFF_FW1;
    const float* fW2d  = wd + 2*OFF_FW2;

    cudaFuncSetAttribute((const void*)down_kernel<256,512>,
                         cudaFuncAttributeMaxDynamicSharedMemorySize, 56*1024);
    cudaFuncSetAttribute((const void*)up_kernel<512,256,256>,
                         cudaFuncAttributeMaxDynamicSharedMemorySize, 50*1024);

    // ---- side stream + events (created once; reused across calls) ----
    static cudaStream_t s = nullptr;
    static cudaEvent_t eP, e0, e1, e2, e3, e4, e5;
    if (!s) {
        cudaStreamCreateWithFlags(&s, cudaStreamNonBlocking);
        cudaEventCreateWithFlags(&eP, cudaEventDisableTiming);
        cudaEventCreateWithFlags(&e0, cudaEventDisableTiming);
        cudaEventCreateWithFlags(&e1, cudaEventDisableTiming);
        cudaEventCreateWithFlags(&e2, cudaEventDisableTiming);
        cudaEventCreateWithFlags(&e3, cudaEventDisableTiming);
        cudaEventCreateWithFlags(&e4, cudaEventDisableTiming);
        cudaEventCreateWithFlags(&e5, cudaEventDisableTiming);
    }

    // ---- preps on main stream ----
    prep_pos4_kernel<<<(Bz*NN0)/256, 256>>>(pos, pos4);
    cudaEventRecord(eP, 0);
    cudaStreamWaitEvent(s, eP, 0);

    // ---- all KNN on side stream (depends only on pos4) ----
    knn16_kernel<32,8><<<dim3(NN1,Bz), 256, 0, s>>>(pos4, NN1, idx0);
    cudaEventRecord(e0, s);
    knn16_kernel<8,8><<<dim3(NN2,Bz), 256, 0, s>>>(pos4, NN2, idx1);
    cudaEventRecord(e1, s);
    knn16_kernel<2,8><<<dim3(NN3,Bz), 256, 0, s>>>(pos4, NN3, idx2);
    cudaEventRecord(e2, s);
    knn3_kernel<4><<<dim3(NN2/8,Bz), 256, 0, s>>>(pos4, NN2, uidx0, ud20);
    cudaEventRecord(e3, s);
    knn3_kernel<16><<<dim3(NN1/8,Bz), 256, 0, s>>>(pos4, NN1, uidx1, ud21);
    cudaEventRecord(e4, s);
    knn3_kernel<64><<<dim3(NN0/8,Bz), 256, 0, s>>>(pos4, NN0, uidx2, ud22);
    cudaEventRecord(e5, s);

    // ---- main stream: weights prep + MLP chain, gated per stage ----
    dup_weights_kernel<<<(W_TOTAL+255)/256, 256>>>(
        d0W1,d0W2,d1W1,d1W2,d2W1,d2W2,u0W,u1W,u2W,fW1,fW2, wd);

    cudaStreamWaitEvent(0, e0, 0);
    down_kernel<3,128><<<dim3(NN1,Bz), 64, (6*16 + 128*16)*sizeof(float)>>>(
        x, pos, idx0, d0W1d,d0b1, d0W2d,d0b2, x1, NN1, NN0*3);
    cudaStreamWaitEvent(0, e1, 0);
    down_kernel<128,256><<<dim3(NN2,Bz), 128, (131*16 + 256*16)*sizeof(float)>>>(
        x1, pos, idx1, d1W1d,d1b1, d1W2d,d1b2, x2, NN2, NN1*128);
    cudaStreamWaitEvent(0, e2, 0);
    down_kernel<256,512><<<dim3(NN3,Bz), 256, (259*16 + 512*16)*sizeof(float)>>>(
        x2, pos, idx2, d2W1d,d2b1, d2W2d,d2b2, x3, NN3, NN2*256);
    cudaStreamWaitEvent(0, e3, 0);
    up_kernel<512,256,256><<<dim3(NN2/16,Bz), 128, 768*16*sizeof(float)>>>(
        x3, x2, uidx0, ud20, u0Wd, u0b, up0, NN2, NN3);
    cudaStreamWaitEvent(0, e4, 0);
    up_kernel<256,128,128><<<dim3(NN1/16,Bz), 64, 384*16*sizeof(float)>>>(
        up0, x1, uidx1, ud21, u1Wd, u1b, up1, NN1, NN2);
    cudaStreamWaitEvent(0, e5, 0);
    up2_final_kernel<<<dim3(NN0/16,Bz), 64>>>(up1, x, pos, uidx2, ud22,
                                              u2Wd,u2b, fW1d,fb1, fW2d,fb2, out);

    // ---- second tuple element: pos0 passthrough ----
    if (out_size >= Bz*NN0*128 + Bz*NN0*3) {
        cudaMemcpyAsync(out + (size_t)Bz*NN0*128, pos,
                        (size_t)Bz*NN0*3*sizeof(float), cudaMemcpyDeviceToDevice);
    }
}

// round 15
// speedup vs baseline: 1.1581x; 1.0340x over previous
#include <cuda_runtime.h>
#include <cfloat>
#include <cstdint>

#define Bz 4
#define NN0 8192
#define NN1 2048
#define NN2 512
#define NN3 128

typedef unsigned long long u64;

__device__ __forceinline__ u64 pack2(float x, float y) {
    u64 r; asm("mov.b64 %0, {%1, %2};" : "=l"(r) : "f"(x), "f"(y)); return r;
}
__device__ __forceinline__ float2 unpack2(u64 v) {
    float2 r; asm("mov.b64 {%0, %1}, %2;" : "=f"(r.x), "=f"(r.y) : "l"(v)); return r;
}
__device__ __forceinline__ u64 ffma2(u64 a, u64 b, u64 c) {
    u64 d; asm("fma.rn.f32x2 %0, %1, %2, %3;" : "=l"(d) : "l"(a), "l"(b), "l"(c)); return d;
}
__device__ __forceinline__ unsigned ordf(float f) {
    unsigned b = __float_as_uint(f);
    return b ^ (((unsigned)((int)b >> 31)) | 0x80000000u);
}
__device__ __forceinline__ float unordf(unsigned m) {
    unsigned b = m ^ ((m & 0x80000000u) ? 0x80000000u : 0xffffffffu);
    return __uint_as_float(b);
}

#define INS3(u, si) do { \
    bool p1 = (u) < m1v; \
    unsigned c1v = p1 ? m1v : (u);  int c1s = p1 ? m1s : (si); \
    m1v = p1 ? (u) : m1v;           m1s = p1 ? (si) : m1s; \
    bool p2 = c1v < m2v; \
    unsigned c2v = p2 ? m2v : c1v;  int c2s = p2 ? m2s : c1s; \
    m2v = p2 ? c1v : m2v;           m2s = p2 ? c1s : m2s; \
    bool p3 = c2v < m3v; \
    m3v = p3 ? c2v : m3v;           m3s = p3 ? c2s : m3s; \
} while(0)

#define FMA16(acc, w, F0, F1, F2, F3) do { \
    acc[0]=ffma2(F0.x,(w),acc[0]); acc[1]=ffma2(F0.y,(w),acc[1]); \
    acc[2]=ffma2(F1.x,(w),acc[2]); acc[3]=ffma2(F1.y,(w),acc[3]); \
    acc[4]=ffma2(F2.x,(w),acc[4]); acc[5]=ffma2(F2.y,(w),acc[5]); \
    acc[6]=ffma2(F3.x,(w),acc[6]); acc[7]=ffma2(F3.y,(w),acc[7]); \
} while(0)

// ---------------- scratch (allocation-free) ----------------
__device__ int   g_idx0[Bz*NN1*16];
__device__ int   g_idx1[Bz*NN2*16];
__device__ int   g_idx2[Bz*NN3*16];
__device__ int   g_uidx0[Bz*NN2*3];
__device__ float g_ud20 [Bz*NN2*3];
__device__ int   g_uidx1[Bz*NN1*3];
__device__ float g_ud21 [Bz*NN1*3];
__device__ int   g_uidx2[Bz*NN0*3];
__device__ float g_ud22 [Bz*NN0*3];
__device__ float g_x1 [Bz*NN1*128];
__device__ float g_x2 [Bz*NN2*256];
__device__ float g_x3 [Bz*NN3*512];
__device__ float g_up0[Bz*NN2*256];
__device__ float g_up1[Bz*NN1*128];
__device__ __align__(16) float g_wdup[2*806656];
__device__ __align__(16) float4 g_pos4[Bz*NN0];

#define OFF_D0W1 0
#define OFF_D0W2 768
#define OFF_D1W1 17152
#define OFF_D1W2 50688
#define OFF_D2W1 116224
#define OFF_D2W2 248832
#define OFF_U0W  510976
#define OFF_U1W  707584
#define OFF_U2W  756736
#define OFF_FW1  773888
#define OFF_FW2  790272
#define W_TOTAL  806656

// ---------------- prep: weight duplication ----------------
__global__ void dup_weights_kernel(const float* __restrict__ s0, const float* __restrict__ s1,
                                   const float* __restrict__ s2, const float* __restrict__ s3,
                                   const float* __restrict__ s4, const float* __restrict__ s5,
                                   const float* __restrict__ s6, const float* __restrict__ s7,
                                   const float* __restrict__ s8, const float* __restrict__ s9,
                                   const float* __restrict__ s10, float* __restrict__ dst) {
    int gid = blockIdx.x*256 + threadIdx.x;
    if (gid >= W_TOTAL) return;
    const int offs[11] = {OFF_D0W1,OFF_D0W2,OFF_D1W1,OFF_D1W2,OFF_D2W1,OFF_D2W2,
                          OFF_U0W,OFF_U1W,OFF_U2W,OFF_FW1,OFF_FW2};
    const float* srcs[11] = {s0,s1,s2,s3,s4,s5,s6,s7,s8,s9,s10};
    int seg = 0;
    #pragma unroll
    for (int i = 1; i < 11; i++) seg = (gid >= offs[i]) ? i : seg;
    float v = srcs[seg][gid - offs[seg]];
    reinterpret_cast<float2*>(dst)[gid] = make_float2(v, v);
}

// ---------------- prep: pos -> (x,y,z,|r|^2) ----------------
__global__ void prep_pos4_kernel(const float* __restrict__ pos, float4* __restrict__ out) {
    int i = blockIdx.x*256 + threadIdx.x;
    float x = pos[3*i+0], y = pos[3*i+1], z = pos[3*i+2];
    float rr = x*x + y*y + z*z;
    out[i] = make_float4(x, y, z, rr);
}

// ---------------- KNN K=16 (validated: CNT=32, NWARP=8) ----------------
template<int CNT, int NWARP>
__global__ void knn16_kernel(const float4* __restrict__ pos4, int Nq, int* __restrict__ oidx,
                             int bofs) {
    __shared__ u64 skey[NWARP*16];
    int b = bofs + blockIdx.y, q = blockIdx.x;
    int lane = threadIdx.x & 31, w = threadIdx.x >> 5;
    const float4* rp = pos4 + (size_t)b*NN0;
    float4 qp = rp[q];
    float qx = qp.x, qy = qp.y, qz = qp.z, qq = qp.w;
    int base = w*CNT*32;

    unsigned ud[CNT];
    unsigned m1v = 0xffffffffu, m2v = 0xffffffffu, m3v = 0xffffffffu;
    int m1s = 0, m2s = 0, m3s = 0;
    #pragma unroll
    for (int i = 0; i < CNT; i++) {
        float4 r4 = rp[base + i*32 + lane];
        float dt = qx*r4.x + qy*r4.y + qz*r4.z;
        float dv = qq + r4.w - 2.0f*dt;
        unsigned u = ordf(dv);
        ud[i] = u;
        INS3(u, i);
    }
    for (int s = 0; s < 16; s++) {
        unsigned mh = __reduce_min_sync(0xffffffffu, m1v);
        unsigned cand = (m1v == mh) ? (unsigned)(m1s*32 + lane) : 0xffffffffu;
        unsigned ml = __reduce_min_sync(0xffffffffu, cand);
        if (lane == 0) skey[w*16 + s] = ((u64)mh << 32) | (unsigned)(base + (int)ml);
        if (cand == ml && m1v == mh) {
            unsigned thr = m1v;
            m1v = m2v; m1s = m2s;
            m2v = m3v; m2s = m3s;
            m3v = 0xffffffffu;
            if (m1v == 0xffffffffu) {   // exhausted buffer: exact rebuild above threshold
                m2v = 0xffffffffu; m3v = 0xffffffffu;
                #pragma unroll
                for (int i = 0; i < CNT; i++) {
                    unsigned u = ud[i];
                    if (u > thr) { INS3(u, i); }
                }
            }
        }
    }
    __syncthreads();
    if (w == 0) {
        u64 head = ~0ull; int ptr = 0;
        if (lane < NWARP) head = skey[lane*16];
        size_t obase = ((size_t)b*Nq + q)*16;
        for (int s = 0; s < 16; s++) {
            unsigned hi = (unsigned)(head >> 32);
            unsigned mh = __reduce_min_sync(0xffffffffu, hi);
            unsigned lo = (hi == mh) ? (unsigned)head : 0xffffffffu;
            unsigned ml = __reduce_min_sync(0xffffffffu, lo);
            if (lane == 0) oidx[obase + s] = (int)ml;
            u64 best = ((u64)mh << 32) | ml;
            if (head == best) {
                ptr++;
                head = (ptr < 16) ? skey[lane*16 + ptr] : ~0ull;
            }
        }
    }
}

// ---------------- KNN K=3, warp variant (validated) ----------------
template<int CNT>
__global__ void knn3_kernel(const float4* __restrict__ pos4, int Nq,
                            int* __restrict__ oidx, float* __restrict__ od2, int bofs) {
    int b = bofs + blockIdx.y;
    int lane = threadIdx.x & 31;
    int q = blockIdx.x*8 + (threadIdx.x >> 5);
    const float4* rp = pos4 + (size_t)b*NN0;
    float4 qp = rp[q];
    float qx = qp.x, qy = qp.y, qz = qp.z, qq = qp.w;

    unsigned m1v = 0xffffffffu, m2v = 0xffffffffu, m3v = 0xffffffffu;
    int m1s = 0, m2s = 0, m3s = 0;
    #pragma unroll 8
    for (int i = 0; i < CNT; i++) {
        float4 r4 = rp[i*32 + lane];
        float dt = qx*r4.x + qy*r4.y + qz*r4.z;
        float dv = qq + r4.w - 2.0f*dt;
        unsigned u = ordf(dv);
        INS3(u, i);
    }
    size_t obase = ((size_t)b*Nq + q)*3;
    #pragma unroll
    for (int s = 0; s < 3; s++) {
        unsigned mh = __reduce_min_sync(0xffffffffu, m1v);
        unsigned cand = (m1v == mh) ? (unsigned)(m1s*32 + lane) : 0xffffffffu;
        unsigned ml = __reduce_min_sync(0xffffffffu, cand);
        if (lane == 0) {
            oidx[obase + s] = (int)ml;
            od2[obase + s]  = fmaxf(unordf(mh), 0.0f);
        }
        if (cand == ml && m1v == mh) {
            m1v = m2v; m1s = m2s;
            m2v = m3v; m2s = m3s;
            m3v = 0xffffffffu;
        }
    }
}

// ---------------- down: gather + 2-layer MLP + max over 16 (one center, j-block=2) ----------------
template<int C_PREV, int C_HID>
__global__ void down_kernel(const float* __restrict__ xprev, const float* __restrict__ pos,
                            const int* __restrict__ idx,
                            const float* __restrict__ W1d, const float* __restrict__ b1,
                            const float* __restrict__ W2d, const float* __restrict__ b2,
                            float* __restrict__ xout, int Nq, int xbs, int bofs) {
    constexpr int CIN = 3 + C_PREV;
    extern __shared__ float sm[];
    float* featT = sm;               // CIN*16
    float* hT    = sm + CIN*16;      // C_HID*16
    __shared__ int nbs[16];
    int b = bofs + blockIdx.y, q = blockIdx.x;
    if (threadIdx.x < 16) nbs[threadIdx.x] = idx[((size_t)b*Nq + q)*16 + threadIdx.x];
    __syncthreads();
    const float* rp = pos + (size_t)b*NN0*3;
    float cx = rp[3*q+0], cy = rp[3*q+1], cz = rp[3*q+2];
    const float* xp = xprev + (size_t)b*xbs;
    for (int e = threadIdx.x; e < 16*CIN; e += blockDim.x) {
        int d = e >> 4, k = e & 15;
        int nb = nbs[k];
        float v;
        if      (d == 0) v = rp[3*nb+0] - cx;
        else if (d == 1) v = rp[3*nb+1] - cy;
        else if (d == 2) v = rp[3*nb+2] - cz;
        else             v = xp[(size_t)nb*C_PREV + (d-3)];
        featT[d*16 + k] = v;
    }
    __syncthreads();
    int j0 = 2*threadIdx.x;
    u64 a0[8], a1[8];
    {
        float2 bb = *reinterpret_cast<const float2*>(&b1[j0]);
        u64 p0 = pack2(bb.x, bb.x), p1 = pack2(bb.y, bb.y);
        #pragma unroll
        for (int i = 0; i < 8; i++) { a0[i] = p0; a1[i] = p1; }
    }
    #pragma unroll 2
    for (int d = 0; d < CIN; d++) {
        ulonglong2 w = *reinterpret_cast<const ulonglong2*>(W1d + 2*(d*C_HID + j0));
        const ulonglong2* f = reinterpret_cast<const ulonglong2*>(featT + d*16);
        ulonglong2 f0 = f[0], f1 = f[1], f2 = f[2], f3 = f[3];
        FMA16(a0, w.x, f0, f1, f2, f3);
        FMA16(a1, w.y, f0, f1, f2, f3);
    }
    {
        float4* h0 = reinterpret_cast<float4*>(hT + (size_t)j0*16);
        float4* h1 = reinterpret_cast<float4*>(hT + (size_t)(j0+1)*16);
        #pragma unroll
        for (int i = 0; i < 4; i++) {
            float2 x0 = unpack2(a0[2*i]), x1 = unpack2(a0[2*i+1]);
            h0[i] = make_float4(fmaxf(x0.x,0.f), fmaxf(x0.y,0.f), fmaxf(x1.x,0.f), fmaxf(x1.y,0.f));
            float2 y0 = unpack2(a1[2*i]), y1 = unpack2(a1[2*i+1]);
            h1[i] = make_float4(fmaxf(y0.x,0.f), fmaxf(y0.y,0.f), fmaxf(y1.x,0.f), fmaxf(y1.y,0.f));
        }
    }
    __syncthreads();
    {
        float2 bb = *reinterpret_cast<const float2*>(&b2[j0]);
        u64 p0 = pack2(bb.x, bb.x), p1 = pack2(bb.y, bb.y);
        #pragma unroll
        for (int i = 0; i < 8; i++) { a0[i] = p0; a1[i] = p1; }
    }
    #pragma unroll 2
    for (int d = 0; d < C_HID; d++) {
        ulonglong2 w = *reinterpret_cast<const ulonglong2*>(W2d + 2*(d*C_HID + j0));
        const ulonglong2* f = reinterpret_cast<const ulonglong2*>(hT + d*16);
        ulonglong2 f0 = f[0], f1 = f[1], f2 = f[2], f3 = f[3];
        FMA16(a0, w.x, f0, f1, f2, f3);
        FMA16(a1, w.y, f0, f1, f2, f3);
    }
    float m0 = -FLT_MAX, m1 = -FLT_MAX;
    #pragma unroll
    for (int i = 0; i < 8; i++) {
        float2 x = unpack2(a0[i]); m0 = fmaxf(m0, fmaxf(x.x, x.y));
        float2 y = unpack2(a1[i]); m1 = fmaxf(m1, fmaxf(y.x, y.y));
    }
    *reinterpret_cast<float2*>(&xout[((size_t)b*Nq + q)*C_HID + j0]) = make_float2(m0, m1);
}

// ---------------- up: 3-NN inverse-distance interp + cat + linear + relu ----------------
template<int C_XC, int C_PRV, int C_OUT>
__global__ void up_kernel(const float* __restrict__ xc, const float* __restrict__ prv,
                          const int* __restrict__ idx, const float* __restrict__ d2,
                          const float* __restrict__ Wd, const float* __restrict__ bias,
                          float* __restrict__ out, int Nq, int Nc, int bofs) {
    constexpr int CIN = C_XC + C_PRV;
    constexpr int QT = 16;
    extern __shared__ float sm[];
    float* featT = sm;
    __shared__ float wsh[QT][3];
    __shared__ int   ish[QT][3];
    int b = bofs + blockIdx.y;
    int q0 = blockIdx.x * QT;
    if (threadIdx.x < QT) {
        int q = q0 + threadIdx.x;
        size_t base = ((size_t)b*Nq + q)*3;
        float w0 = 1.0f/(d2[base+0] + 1e-8f);
        float w1 = 1.0f/(d2[base+1] + 1e-8f);
        float w2 = 1.0f/(d2[base+2] + 1e-8f);
        float s = w0 + w1 + w2;
        wsh[threadIdx.x][0] = w0/s; wsh[threadIdx.x][1] = w1/s; wsh[threadIdx.x][2] = w2/s;
        ish[threadIdx.x][0] = idx[base+0]; ish[threadIdx.x][1] = idx[base+1]; ish[threadIdx.x][2] = idx[base+2];
    }
    __syncthreads();
    const float* xcb = xc + (size_t)b*Nc*C_XC;
    for (int e = threadIdx.x; e < CIN*QT; e += blockDim.x) {
        int d = e >> 4, qq = e & 15;
        float v;
        if (d < C_XC) {
            v = wsh[qq][0]*xcb[(size_t)ish[qq][0]*C_XC + d]
              + wsh[qq][1]*xcb[(size_t)ish[qq][1]*C_XC + d]
              + wsh[qq][2]*xcb[(size_t)ish[qq][2]*C_XC + d];
        } else {
            v = prv[((size_t)b*Nq + q0 + qq)*C_PRV + (d - C_XC)];
        }
        featT[e] = v;
    }
    __syncthreads();
    int j0 = 2*threadIdx.x;
    u64 a0[8], a1[8];
    {
        float2 bb = *reinterpret_cast<const float2*>(&bias[j0]);
        u64 p0 = pack2(bb.x, bb.x), p1 = pack2(bb.y, bb.y);
        #pragma unroll
        for (int i = 0; i < 8; i++) { a0[i] = p0; a1[i] = p1; }
    }
    #pragma unroll 2
    for (int d = 0; d < CIN; d++) {
        ulonglong2 w = *reinterpret_cast<const ulonglong2*>(Wd + 2*(d*C_OUT + j0));
        const ulonglong2* f = reinterpret_cast<const ulonglong2*>(featT + d*QT);
        ulonglong2 f0 = f[0], f1 = f[1], f2 = f[2], f3 = f[3];
        FMA16(a0, w.x, f0, f1, f2, f3);
        FMA16(a1, w.y, f0, f1, f2, f3);
    }
    size_t obase = ((size_t)b*Nq + q0)*C_OUT + j0;
    #pragma unroll
    for (int i = 0; i < 8; i++) {
        float2 x = unpack2(a0[i]), y = unpack2(a1[i]);
        *reinterpret_cast<float2*>(&out[obase + (size_t)(2*i+0)*C_OUT]) =
            make_float2(fmaxf(x.x,0.f), fmaxf(y.x,0.f));
        *reinterpret_cast<float2*>(&out[obase + (size_t)(2*i+1)*C_OUT]) =
            make_float2(fmaxf(x.y,0.f), fmaxf(y.y,0.f));
    }
}

// ---------------- fused: up2 + final MLP (QT=16, 64 threads) ----------------
__global__ void up2_final_kernel(const float* __restrict__ up1,
                                 const float* __restrict__ x0, const float* __restrict__ pos0,
                                 const int* __restrict__ idx, const float* __restrict__ d2,
                                 const float* __restrict__ u2Wd, const float* __restrict__ u2b,
                                 const float* __restrict__ fW1d, const float* __restrict__ fb1,
                                 const float* __restrict__ fW2d, const float* __restrict__ fb2,
                                 float* __restrict__ out, int bofs) {
    constexpr int QT = 16;
    __shared__ float featT[134*QT];
    __shared__ float h1T[128*QT];
    __shared__ float wsh[QT][3];
    __shared__ int   ish[QT][3];
    int b = bofs + blockIdx.y;
    int q0 = blockIdx.x * QT;
    if (threadIdx.x < QT) {
        int q = q0 + threadIdx.x;
        size_t base = ((size_t)b*NN0 + q)*3;
        float w0 = 1.0f/(d2[base+0] + 1e-8f);
        float w1 = 1.0f/(d2[base+1] + 1e-8f);
        float w2 = 1.0f/(d2[base+2] + 1e-8f);
        float s = w0 + w1 + w2;
        wsh[threadIdx.x][0] = w0/s; wsh[threadIdx.x][1] = w1/s; wsh[threadIdx.x][2] = w2/s;
        ish[threadIdx.x][0] = idx[base+0]; ish[threadIdx.x][1] = idx[base+1]; ish[threadIdx.x][2] = idx[base+2];
    }
    __syncthreads();
    const float* xcb = up1 + (size_t)b*NN1*128;
    for (int e = threadIdx.x; e < 134*QT; e += 64) {
        int d = e >> 4, qq = e & 15;
        float v;
        if (d < 128) {
            v = wsh[qq][0]*xcb[(size_t)ish[qq][0]*128 + d]
              + wsh[qq][1]*xcb[(size_t)ish[qq][1]*128 + d]
              + wsh[qq][2]*xcb[(size_t)ish[qq][2]*128 + d];
        } else if (d < 131) {
            v = x0  [((size_t)b*NN0 + q0 + qq)*3 + (d-128)];
        } else {
            v = pos0[((size_t)b*NN0 + q0 + qq)*3 + (d-131)];
        }
        featT[e] = v;
    }
    __syncthreads();
    int j0 = 2*threadIdx.x;
    u64 a0[8], a1[8];

    {
        float2 bb = *reinterpret_cast<const float2*>(&u2b[j0]);
        u64 p0 = pack2(bb.x, bb.x), p1 = pack2(bb.y, bb.y);
        #pragma unroll
        for (int i = 0; i < 8; i++) { a0[i] = p0; a1[i] = p1; }
    }
    #pragma unroll 2
    for (int d = 0; d < 134; d++) {
        ulonglong2 w = *reinterpret_cast<const ulonglong2*>(u2Wd + 2*(d*128 + j0));
        const ulonglong2* f = reinterpret_cast<const ulonglong2*>(featT + d*QT);
        ulonglong2 f0 = f[0], f1 = f[1], f2 = f[2], f3 = f[3];
        FMA16(a0, w.x, f0, f1, f2, f3);
        FMA16(a1, w.y, f0, f1, f2, f3);
    }
    {
        float4* h0 = reinterpret_cast<float4*>(h1T + (size_t)j0*QT);
        float4* h1 = reinterpret_cast<float4*>(h1T + (size_t)(j0+1)*QT);
        #pragma unroll
        for (int i = 0; i < 4; i++) {
            float2 x0v = unpack2(a0[2*i]), x1v = unpack2(a0[2*i+1]);
            h0[i] = make_float4(fmaxf(x0v.x,0.f), fmaxf(x0v.y,0.f), fmaxf(x1v.x,0.f), fmaxf(x1v.y,0.f));
            float2 y0v = unpack2(a1[2*i]), y1v = unpack2(a1[2*i+1]);
            h1[i] = make_float4(fmaxf(y0v.x,0.f), fmaxf(y0v.y,0.f), fmaxf(y1v.x,0.f), fmaxf(y1v.y,0.f));
        }
    }
    __syncthreads();

    {
        float2 bb = *reinterpret_cast<const float2*>(&fb1[j0]);
        u64 p0 = pack2(bb.x, bb.x), p1 = pack2(bb.y, bb.y);
        #pragma unroll
        for (int i = 0; i < 8; i++) { a0[i] = p0; a1[i] = p1; }
    }
    #pragma unroll 2
    for (int d = 0; d < 128; d++) {
        ulonglong2 w = *reinterpret_cast<const ulonglong2*>(fW1d + 2*(d*128 + j0));
        const ulonglong2* f = reinterpret_cast<const ulonglong2*>(h1T + d*QT);
        ulonglong2 f0 = f[0], f1 = f[1], f2 = f[2], f3 = f[3];
        FMA16(a0, w.x, f0, f1, f2, f3);
        FMA16(a1, w.y, f0, f1, f2, f3);
    }
    __syncthreads();
    {
        float4* h0 = reinterpret_cast<float4*>(featT + (size_t)j0*QT);
        float4* h1 = reinterpret_cast<float4*>(featT + (size_t)(j0+1)*QT);
        #pragma unroll
        for (int i = 0; i < 4; i++) {
            float2 x0v = unpack2(a0[2*i]), x1v = unpack2(a0[2*i+1]);
            h0[i] = make_float4(fmaxf(x0v.x,0.f), fmaxf(x0v.y,0.f), fmaxf(x1v.x,0.f), fmaxf(x1v.y,0.f));
            float2 y0v = unpack2(a1[2*i]), y1v = unpack2(a1[2*i+1]);
            h1[i] = make_float4(fmaxf(y0v.x,0.f), fmaxf(y0v.y,0.f), fmaxf(y1v.x,0.f), fmaxf(y1v.y,0.f));
        }
    }
    __syncthreads();

    {
        float2 bb = *reinterpret_cast<const float2*>(&fb2[j0]);
        u64 p0 = pack2(bb.x, bb.x), p1 = pack2(bb.y, bb.y);
        #pragma unroll
        for (int i = 0; i < 8; i++) { a0[i] = p0; a1[i] = p1; }
    }
    #pragma unroll 2
    for (int d = 0; d < 128; d++) {
        ulonglong2 w = *reinterpret_cast<const ulonglong2*>(fW2d + 2*(d*128 + j0));
        const ulonglong2* f = reinterpret_cast<const ulonglong2*>(featT + d*QT);
        ulonglong2 f0 = f[0], f1 = f[1], f2 = f[2], f3 = f[3];
        FMA16(a0, w.x, f0, f1, f2, f3);
        FMA16(a1, w.y, f0, f1, f2, f3);
    }
    size_t obase = ((size_t)b*NN0 + q0)*128 + j0;
    #pragma unroll
    for (int i = 0; i < 8; i++) {
        float2 x = unpack2(a0[i]), y = unpack2(a1[i]);
        *reinterpret_cast<float2*>(&out[obase + (size_t)(2*i+0)*128]) = make_float2(x.x, y.x);
        *reinterpret_cast<float2*>(&out[obase + (size_t)(2*i+1)*128]) = make_float2(x.y, y.y);
    }
}

// ---------------- host launch ----------------
extern "C" void kernel_launch(void* const* d_in, const int* in_sizes, int n_in,
                              void* d_out, int out_size) {
    const float* x    = (const float*)d_in[0];
    const float* pos  = (const float*)d_in[1];
    const float* d0W1 = (const float*)d_in[2];
    const float* d0b1 = (const float*)d_in[3];
    const float* d0W2 = (const float*)d_in[4];
    const float* d0b2 = (const float*)d_in[5];
    const float* d1W1 = (const float*)d_in[6];
    const float* d1b1 = (const float*)d_in[7];
    const float* d1W2 = (const float*)d_in[8];
    const float* d1b2 = (const float*)d_in[9];
    const float* d2W1 = (const float*)d_in[10];
    const float* d2b1 = (const float*)d_in[11];
    const float* d2W2 = (const float*)d_in[12];
    const float* d2b2 = (const float*)d_in[13];
    const float* u0W  = (const float*)d_in[14];
    const float* u0b  = (const float*)d_in[15];
    const float* u1W  = (const float*)d_in[16];
    const float* u1b  = (const float*)d_in[17];
    const float* u2W  = (const float*)d_in[18];
    const float* u2b  = (const float*)d_in[19];
    const float* fW1  = (const float*)d_in[20];
    const float* fb1  = (const float*)d_in[21];
    const float* fW2  = (const float*)d_in[22];
    const float* fb2  = (const float*)d_in[23];
    float* out = (float*)d_out;

    int *idx0, *idx1, *idx2, *uidx0, *uidx1, *uidx2;
    float *ud20, *ud21, *ud22, *x1, *x2, *x3, *up0, *up1, *wd;
    float4* pos4;
    cudaGetSymbolAddress((void**)&idx0,  g_idx0);
    cudaGetSymbolAddress((void**)&idx1,  g_idx1);
    cudaGetSymbolAddress((void**)&idx2,  g_idx2);
    cudaGetSymbolAddress((void**)&uidx0, g_uidx0);
    cudaGetSymbolAddress((void**)&uidx1, g_uidx1);
    cudaGetSymbolAddress((void**)&uidx2, g_uidx2);
    cudaGetSymbolAddress((void**)&ud20,  g_ud20);
    cudaGetSymbolAddress((void**)&ud21,  g_ud21);
    cudaGetSymbolAddress((void**)&ud22,  g_ud22);
    cudaGetSymbolAddress((void**)&x1,    g_x1);
    cudaGetSymbolAddress((void**)&x2,    g_x2);
    cudaGetSymbolAddress((void**)&x3,    g_x3);
    cudaGetSymbolAddress((void**)&up0,   g_up0);
    cudaGetSymbolAddress((void**)&up1,   g_up1);
    cudaGetSymbolAddress((void**)&wd,    g_wdup);
    cudaGetSymbolAddress((void**)&pos4,  g_pos4);

    const float* d0W1d = wd + 2*OFF_D0W1;
    const float* d0W2d = wd + 2*OFF_D0W2;
    const float* d1W1d = wd + 2*OFF_D1W1;
    const float* d1W2d = wd + 2*OFF_D1W2;
    const float* d2W1d = wd + 2*OFF_D2W1;
    const float* d2W2d = wd + 2*OFF_D2W2;
    const float* u0Wd  = wd + 2*OFF_U0W;
    const float* u1Wd  = wd + 2*OFF_U1W;
    const float* u2Wd  = wd + 2*OFF_U2W;
    const float* fW1d  = wd + 2*OFF_FW1;
    const float* fW2d  = wd + 2*OFF_FW2;

    cudaFuncSetAttribute((const void*)down_kernel<256,512>,
                         cudaFuncAttributeMaxDynamicSharedMemorySize, 56*1024);
    cudaFuncSetAttribute((const void*)up_kernel<512,256,256>,
                         cudaFuncAttributeMaxDynamicSharedMemorySize, 50*1024);

    // ---- streams + events (created once; reused across calls) ----
    static cudaStream_t sB = nullptr, sKA = nullptr, sKB = nullptr;
    static cudaEvent_t eP, eW, eFB;
    static cudaEvent_t eA[6], eB[6];
    if (!sB) {
        cudaStreamCreateWithFlags(&sB,  cudaStreamNonBlocking);
        cudaStreamCreateWithFlags(&sKA, cudaStreamNonBlocking);
        cudaStreamCreateWithFlags(&sKB, cudaStreamNonBlocking);
        cudaEventCreateWithFlags(&eP,  cudaEventDisableTiming);
        cudaEventCreateWithFlags(&eW,  cudaEventDisableTiming);
        cudaEventCreateWithFlags(&eFB, cudaEventDisableTiming);
        for (int i = 0; i < 6; i++) {
            cudaEventCreateWithFlags(&eA[i], cudaEventDisableTiming);
            cudaEventCreateWithFlags(&eB[i], cudaEventDisableTiming);
        }
    }

    // ---- preps on main stream ----
    prep_pos4_kernel<<<(Bz*NN0)/256, 256>>>(pos, pos4);
    cudaEventRecord(eP, 0);
    cudaStreamWaitEvent(sKA, eP, 0);
    cudaStreamWaitEvent(sKB, eP, 0);

    // ---- KNN chains (batch 0-1 on sKA; batch 2-3 on sKB) ----
    knn16_kernel<32,8><<<dim3(NN1,2), 256, 0, sKA>>>(pos4, NN1, idx0, 0);
    cudaEventRecord(eA[0], sKA);
    knn16_kernel<8,8><<<dim3(NN2,2), 256, 0, sKA>>>(pos4, NN2, idx1, 0);
    cudaEventRecord(eA[1], sKA);
    knn16_kernel<2,8><<<dim3(NN3,2), 256, 0, sKA>>>(pos4, NN3, idx2, 0);
    cudaEventRecord(eA[2], sKA);
    knn3_kernel<4><<<dim3(NN2/8,2), 256, 0, sKA>>>(pos4, NN2, uidx0, ud20, 0);
    cudaEventRecord(eA[3], sKA);
    knn3_kernel<16><<<dim3(NN1/8,2), 256, 0, sKA>>>(pos4, NN1, uidx1, ud21, 0);
    cudaEventRecord(eA[4], sKA);
    knn3_kernel<64><<<dim3(NN0/8,2), 256, 0, sKA>>>(pos4, NN0, uidx2, ud22, 0);
    cudaEventRecord(eA[5], sKA);

    knn16_kernel<32,8><<<dim3(NN1,2), 256, 0, sKB>>>(pos4, NN1, idx0, 2);
    cudaEventRecord(eB[0], sKB);
    knn16_kernel<8,8><<<dim3(NN2,2), 256, 0, sKB>>>(pos4, NN2, idx1, 2);
    cudaEventRecord(eB[1], sKB);
    knn16_kernel<2,8><<<dim3(NN3,2), 256, 0, sKB>>>(pos4, NN3, idx2, 2);
    cudaEventRecord(eB[2], sKB);
    knn3_kernel<4><<<dim3(NN2/8,2), 256, 0, sKB>>>(pos4, NN2, uidx0, ud20, 2);
    cudaEventRecord(eB[3], sKB);
    knn3_kernel<16><<<dim3(NN1/8,2), 256, 0, sKB>>>(pos4, NN1, uidx1, ud21, 2);
    cudaEventRecord(eB[4], sKB);
    knn3_kernel<64><<<dim3(NN0/8,2), 256, 0, sKB>>>(pos4, NN0, uidx2, ud22, 2);
    cudaEventRecord(eB[5], sKB);

    // ---- weights prep on main stream; chain B waits on it ----
    dup_weights_kernel<<<(W_TOTAL+255)/256, 256>>>(
        d0W1,d0W2,d1W1,d1W2,d2W1,d2W2,u0W,u1W,u2W,fW1,fW2, wd);
    cudaEventRecord(eW, 0);
    cudaStreamWaitEvent(sB, eW, 0);

    // ---- chain A (batches 0-1) on main stream ----
    cudaStreamWaitEvent(0, eA[0], 0);
    down_kernel<3,128><<<dim3(NN1,2), 64, (6*16 + 128*16)*sizeof(float)>>>(
        x, pos, idx0, d0W1d,d0b1, d0W2d,d0b2, x1, NN1, NN0*3, 0);
    cudaStreamWaitEvent(0, eA[1], 0);
    down_kernel<128,256><<<dim3(NN2,2), 128, (131*16 + 256*16)*sizeof(float)>>>(
        x1, pos, idx1, d1W1d,d1b1, d1W2d,d1b2, x2, NN2, NN1*128, 0);
    cudaStreamWaitEvent(0, eA[2], 0);
    down_kernel<256,512><<<dim3(NN3,2), 256, (259*16 + 512*16)*sizeof(float)>>>(
        x2, pos, idx2, d2W1d,d2b1, d2W2d,d2b2, x3, NN3, NN2*256, 0);
    cudaStreamWaitEvent(0, eA[3], 0);
    up_kernel<512,256,256><<<dim3(NN2/16,2), 128, 768*16*sizeof(float)>>>(
        x3, x2, uidx0, ud20, u0Wd, u0b, up0, NN2, NN3, 0);
    cudaStreamWaitEvent(0, eA[4], 0);
    up_kernel<256,128,128><<<dim3(NN1/16,2), 64, 384*16*sizeof(float)>>>(
        up0, x1, uidx1, ud21, u1Wd, u1b, up1, NN1, NN2, 0);
    cudaStreamWaitEvent(0, eA[5], 0);
    up2_final_kernel<<<dim3(NN0/16,2), 64>>>(up1, x, pos, uidx2, ud22,
                                             u2Wd,u2b, fW1d,fb1, fW2d,fb2, out, 0);

    // ---- chain B (batches 2-3) on sB ----
    cudaStreamWaitEvent(sB, eB[0], 0);
    down_kernel<3,128><<<dim3(NN1,2), 64, (6*16 + 128*16)*sizeof(float), sB>>>(
        x, pos, idx0, d0W1d,d0b1, d0W2d,d0b2, x1, NN1, NN0*3, 2);
    cudaStreamWaitEvent(sB, eB[1], 0);
    down_kernel<128,256><<<dim3(NN2,2), 128, (131*16 + 256*16)*sizeof(float), sB>>>(
        x1, pos, idx1, d1W1d,d1b1, d1W2d,d1b2, x2, NN2, NN1*128, 2);
    cudaStreamWaitEvent(sB, eB[2], 0);
    down_kernel<256,512><<<dim3(NN3,2), 256, (259*16 + 512*16)*sizeof(float), sB>>>(
        x2, pos, idx2, d2W1d,d2b1, d2W2d,d2b2, x3, NN3, NN2*256, 2);
    cudaStreamWaitEvent(sB, eB[3], 0);
    up_kernel<512,256,256><<<dim3(NN2/16,2), 128, 768*16*sizeof(float), sB>>>(
        x3, x2, uidx0, ud20, u0Wd, u0b, up0, NN2, NN3, 2);
    cudaStreamWaitEvent(sB, eB[4], 0);
    up_kernel<256,128,128><<<dim3(NN1/16,2), 64, 384*16*sizeof(float), sB>>>(
        up0, x1, uidx1, ud21, u1Wd, u1b, up1, NN1, NN2, 2);
    cudaStreamWaitEvent(sB, eB[5], 0);
    up2_final_kernel<<<dim3(NN0/16,2), 64, 0, sB>>>(up1, x, pos, uidx2, ud22,
                                                    u2Wd,u2b, fW1d,fb1, fW2d,fb2, out, 2);
    cudaEventRecord(eFB, sB);
    cudaStreamWaitEvent(0, eFB, 0);

    // ---- second tuple element: pos0 passthrough ----
    if (out_size >= Bz*NN0*128 + Bz*NN0*3) {
        cudaMemcpyAsync(out + (size_t)Bz*NN0*128, pos,
                        (size_t)Bz*NN0*3*sizeof(float), cudaMemcpyDeviceToDevice);
    }
}